// round 4
// baseline (speedup 1.0000x reference)
#include <cuda_runtime.h>
#include <math.h>
#include <stdint.h>

#define NG   256
#define NG3  16777216
#define NW   (NG3/32)           // 524288 z-words per mask
#define SP   0.390625f          // 100/256, exact in f32

// combined grid: per z-word, lo32 = occ bits, hi32 = prot bits
static __device__ unsigned long long g_bits[NW];
static __device__ uint32_t           g_solvb[NW];
static __device__ float              g_fA[NG3];     // zy-blurred intermediate

// ---- zero the splat grid (4 MB) ----
__global__ void zero_kernel() {
    unsigned i = blockIdx.x * blockDim.x + threadIdx.x;
    if (i < NW / 2)
        reinterpret_cast<uint4*>(g_bits)[i] = make_uint4(0u, 0u, 0u, 0u);
}

// smallest float T with (s < T) <=> (sqrt_rn(s) < R)
__device__ __forceinline__ float cut_threshold(float R) {
    float t = __fmul_rn(R, R);
    while (__fsqrt_rn(t) >= R)
        t = __uint_as_float(__float_as_uint(t) - 1u);
    while (__fsqrt_rn(__uint_as_float(__float_as_uint(t) + 1u)) < R)
        t = __uint_as_float(__float_as_uint(t) + 1u);
    return __uint_as_float(__float_as_uint(t) + 1u);
}

// ---- splat: one warp per atom, branch-free 17-cell mask per (dx,dy) ----
__global__ void splat_kernel(const float* __restrict__ xyz,
                             const float* __restrict__ vdw,
                             int n_atoms) {
    int a = blockIdx.x * 4 + (threadIdx.x >> 5);
    if (a >= n_atoms) return;
    int lane = threadIdx.x & 31;
    float ax = xyz[3*a], ay = xyz[3*a+1], az = xyz[3*a+2];
    float vr = vdw[a];
    float R    = __fadd_rn(vr, 1.1f);
    float Tocc = cut_threshold(R);
    float Tpro = cut_threshold(vr);

    int bx = (int)floorf(__fdiv_rn(ax, SP));
    int by = (int)floorf(__fdiv_rn(ay, SP));
    int bz = (int)floorf(__fdiv_rn(az, SP));
    int zs = bz - 8;

    for (int p = lane; p < 289; p += 32) {
        int dx = p / 17 - 8;
        int dy = p % 17 - 8;
        int cx = bx + dx, cy = by + dy;
        float rx = __fsub_rn(__fmul_rn((float)cx, SP), ax);
        float ry = __fsub_rn(__fmul_rn((float)cy, SP), ay);
        float rxy2 = __fadd_rn(__fmul_rn(rx, rx), __fmul_rn(ry, ry));
        if (rxy2 >= Tocc) continue;           // exact: s >= rxy2

        unsigned mO = 0, mP = 0;
        #pragma unroll
        for (int j = 0; j < 17; ++j) {        // exact ref predicate per cell
            float rz = __fsub_rn(__fmul_rn((float)(zs + j), SP), az);
            float s  = __fadd_rn(rxy2, __fmul_rn(rz, rz));
            if (s < Tocc) mO |= 1u << j;
            if (s < Tpro) mP |= 1u << j;
        }
        if (!mO) continue;

        int s0 = zs & 255;
        int w0 = s0 >> 5, off = s0 & 31;
        unsigned long long osh = ((unsigned long long)mO) << off;
        unsigned long long psh = ((unsigned long long)mP) << off;
        int colbase = ((cx & 255) << 8) | (cy & 255);
        unsigned long long v0 = ((unsigned long long)(unsigned)psh << 32)
                              |  (unsigned long long)(unsigned)osh;
        unsigned long long v1 = ((unsigned long long)(unsigned)(psh >> 32) << 32)
                              |  (unsigned long long)(unsigned)(osh >> 32);
        if (v0) atomicOr(&g_bits[(w0 << 16) + colbase], v0);
        if (v1) atomicOr(&g_bits[((((w0 + 1) & 7)) << 16) + colbase], v1);
    }
}

// ---- classify: solv = ds | (nb & ~prot), bitwise erosion ----
__global__ void classify_kernel() {
    __shared__ uint32_t sD0[8 * 400];
    __shared__ uint32_t sD1[8 * 400];
    __shared__ uint32_t sD2[8 * 400];
    int bx0 = (blockIdx.x & 15) * 16;
    int by0 = (blockIdx.x >> 4) * 16;
    int t = threadIdx.x;

    for (int c = t; c < 400; c += 256) {
        int lx = c % 20, ly = c / 20;
        int gx = (bx0 + lx - 2) & 255;
        int gy = (by0 + ly - 2) & 255;
        int col = (gx << 8) | gy;
        uint32_t ds[8], d1[8], d2[8];
        #pragma unroll
        for (int i = 0; i < 8; i++)
            ds[i] = ~(uint32_t)g_bits[(i << 16) + col];
        #pragma unroll
        for (int i = 0; i < 8; i++)
            d1[i] = ds[i] | (ds[i] << 1) | (ds[(i+7)&7] >> 31)
                          | (ds[i] >> 1) | (ds[(i+1)&7] << 31);
        #pragma unroll
        for (int i = 0; i < 8; i++)
            d2[i] = d1[i] | (d1[i] << 1) | (d1[(i+7)&7] >> 31)
                          | (d1[i] >> 1) | (d1[(i+1)&7] << 31);
        #pragma unroll
        for (int i = 0; i < 8; i++) {
            sD0[i*400 + c] = ds[i];
            sD1[i*400 + c] = d1[i];
            sD2[i*400 + c] = d2[i];
        }
    }
    __syncthreads();

    int lx = (t & 15) + 2, ly = (t >> 4) + 2;
    int gx = (bx0 + lx - 2) & 255;
    int gy = (by0 + ly - 2) & 255;
    int col = (gx << 8) | gy;
    int cc = ly * 20 + lx;
    #pragma unroll
    for (int i = 0; i < 8; i++) {
        const uint32_t* D0 = sD0 + i * 400;
        const uint32_t* D1 = sD1 + i * 400;
        const uint32_t* D2 = sD2 + i * 400;
        uint32_t nb =
            D2[cc] | D2[cc+1]  | D2[cc-1]  | D2[cc+20] | D2[cc-20] |
            D1[cc+21] | D1[cc+19] | D1[cc-19] | D1[cc-21] |
            D1[cc+2]  | D1[cc-2]  | D1[cc+40] | D1[cc-40] |
            D0[cc+22] | D0[cc+18] | D0[cc-18] | D0[cc-22] |
            D0[cc+41] | D0[cc+39] | D0[cc-39] | D0[cc-41];
        uint32_t p = (uint32_t)(g_bits[(i << 16) + col] >> 32);
        g_solvb[(i << 16) + col] = D0[cc] | (nb & ~p);
    }
}

// ---- K1: fused z+y blur from bits (3 LUT lookups per float4) ----
// zblur4 is linear in its 6 input bits, so for the two y-neighbors:
// zblur4(im) + zblur4(ip) = zblur4(im^ip) + 2*zblur4(im&ip)
__global__ __launch_bounds__(256)
void blur_zy_kernel(double a0d, double a1d) {
    __shared__ float4 sLc[64], sLe[64];
    int t = threadIdx.x;
    if (t < 128) {
        int grp = t >> 6, e = t & 63;
        double b[6];
        #pragma unroll
        for (int q = 0; q < 6; q++) b[q] = (double)((e >> q) & 1);
        double sc = (grp == 0) ? a0d : a1d;    // y-axis weight
        float4 v = make_float4(
            (float)((a1d*b[0] + a0d*b[1] + a1d*b[2]) * sc),
            (float)((a1d*b[1] + a0d*b[2] + a1d*b[3]) * sc),
            (float)((a1d*b[2] + a0d*b[3] + a1d*b[4]) * sc),
            (float)((a1d*b[3] + a0d*b[4] + a1d*b[5]) * sc));
        if (grp == 0) sLc[e] = v; else sLe[e] = v;
    }
    __syncthreads();

    int gt  = blockIdx.x * 256 + t;
    int col = gt >> 6;                 // (x<<8)|y ; 64 consecutive threads/column
    int x   = col >> 8, y = col & 255;
    int z   = (gt & 63) << 2;
    int zm  = (z - 1) & 255;
    int wA  = zm >> 5, wB = (wA + 1) & 7, off = zm & 31;
    int cm  = (x << 8) | ((y + 255) & 255);
    int cp  = (x << 8) | ((y + 1)   & 255);

    uint32_t ic = __funnelshift_r(g_solvb[(wA<<16)+col], g_solvb[(wB<<16)+col], off) & 63;
    uint32_t im = __funnelshift_r(g_solvb[(wA<<16)+cm],  g_solvb[(wB<<16)+cm],  off) & 63;
    uint32_t ip = __funnelshift_r(g_solvb[(wA<<16)+cp],  g_solvb[(wB<<16)+cp],  off) & 63;
    uint32_t e0 = im ^ ip, e1 = im & ip;

    float4 o  = sLc[ic];
    float4 l0 = sLe[e0];
    float4 l1 = sLe[e1];
    o.x += l0.x; o.x = fmaf(2.0f, l1.x, o.x);
    o.y += l0.y; o.y = fmaf(2.0f, l1.y, o.y);
    o.z += l0.z; o.z = fmaf(2.0f, l1.z, o.z);
    o.w += l0.w; o.w = fmaf(2.0f, l1.w, o.w);
    reinterpret_cast<float4*>(g_fA)[gt] = o;
}

// ---- K2: x pass, rolling 3-window, 8 x-cells per thread ----
__global__ __launch_bounds__(256)
void blur_x_kernel(float4* __restrict__ out, float a0, float a1) {
    int cid = blockIdx.x * 256 + threadIdx.x;    // 524288 threads
    int xc  = cid >> 14;                         // 32 x-chunks of 8
    int yz  = cid & 16383;                       // (y<<6)|zgroup : lane<->z contiguous
    const float4* A = reinterpret_cast<const float4*>(g_fA);

    int x0 = xc << 3;
    float4 m = A[((((x0 + 255) & 255) << 14) | yz)];
    float4 c = A[((x0 << 14) | yz)];
    #pragma unroll
    for (int j = 0; j < 8; ++j) {
        int xn = (x0 + j + 1) & 255;
        float4 p = A[((xn << 14) | yz)];
        float4 o;
        o.x = fmaf(a1, m.x + p.x, a0 * c.x);
        o.y = fmaf(a1, m.y + p.y, a0 * c.y);
        o.z = fmaf(a1, m.z + p.z, a0 * c.z);
        o.w = fmaf(a1, m.w + p.w, a0 * c.w);
        out[(((x0 + j) << 14) | yz)] = o;
        m = c; c = p;
    }
}

extern "C" void kernel_launch(void* const* d_in, const int* in_sizes, int n_in,
                              void* d_out, int out_size) {
    const float* xyz = (const float*)d_in[0];
    const float* vdw = (const float*)d_in[1];
    int n_atoms = in_sizes[1];

    double sigma = 1.1 / (100.0 / 256.0) / 4.0;
    double w = exp(-1.0 / (2.0 * sigma * sigma));
    double s = 1.0 + 2.0 * w;
    double a0d = 1.0 / s, a1d = w / s;

    zero_kernel     <<<1024, 256>>>();
    splat_kernel    <<<(n_atoms + 3) / 4, 128>>>(xyz, vdw, n_atoms);
    classify_kernel <<<256, 256>>>();
    blur_zy_kernel  <<<16384, 256>>>(a0d, a1d);
    blur_x_kernel   <<<2048, 256>>>((float4*)d_out, (float)a0d, (float)a1d);
}

// round 5
// speedup vs baseline: 2.4053x; 2.4053x over previous
#include <cuda_runtime.h>
#include <math.h>
#include <stdint.h>

#define NG   256
#define NG3  16777216
#define NW   (NG3/32)           // 524288 z-words per mask
#define SP   0.390625f          // 100/256, exact in f32

// combined grid: per z-word, lo32 = occ bits, hi32 = prot bits
static __device__ unsigned long long g_bits[NW];
static __device__ uint32_t           g_solvb[NW];
static __device__ float              g_fA[NG3];     // zy-blurred intermediate

// ---- zero the splat grid (4 MB) ----
__global__ void zero_kernel() {
    unsigned i = blockIdx.x * blockDim.x + threadIdx.x;
    if (i < NW / 2)
        reinterpret_cast<uint4*>(g_bits)[i] = make_uint4(0u, 0u, 0u, 0u);
}

// smallest float T with (s < T) <=> (sqrt_rn(s) < R)
__device__ __forceinline__ float cut_threshold(float R) {
    float t = __fmul_rn(R, R);
    while (__fsqrt_rn(t) >= R)
        t = __uint_as_float(__float_as_uint(t) - 1u);
    while (__fsqrt_rn(__uint_as_float(__float_as_uint(t) + 1u)) < R)
        t = __uint_as_float(__float_as_uint(t) + 1u);
    return __uint_as_float(__float_as_uint(t) + 1u);
}

// ---- splat: one warp per atom, branch-free 17-cell mask per (dx,dy) ----
__global__ void splat_kernel(const float* __restrict__ xyz,
                             const float* __restrict__ vdw,
                             int n_atoms) {
    int a = blockIdx.x * 4 + (threadIdx.x >> 5);
    if (a >= n_atoms) return;
    int lane = threadIdx.x & 31;
    float ax = xyz[3*a], ay = xyz[3*a+1], az = xyz[3*a+2];
    float vr = vdw[a];
    float R    = __fadd_rn(vr, 1.1f);
    float Tocc = cut_threshold(R);
    float Tpro = cut_threshold(vr);

    int bx = (int)floorf(__fdiv_rn(ax, SP));
    int by = (int)floorf(__fdiv_rn(ay, SP));
    int bz = (int)floorf(__fdiv_rn(az, SP));
    int zs = bz - 8;

    for (int p = lane; p < 289; p += 32) {
        int dx = p / 17 - 8;
        int dy = p % 17 - 8;
        int cx = bx + dx, cy = by + dy;
        float rx = __fsub_rn(__fmul_rn((float)cx, SP), ax);
        float ry = __fsub_rn(__fmul_rn((float)cy, SP), ay);
        float rxy2 = __fadd_rn(__fmul_rn(rx, rx), __fmul_rn(ry, ry));
        if (rxy2 >= Tocc) continue;           // exact: s >= rxy2

        unsigned mO = 0, mP = 0;
        #pragma unroll
        for (int j = 0; j < 17; ++j) {        // exact ref predicate per cell
            float rz = __fsub_rn(__fmul_rn((float)(zs + j), SP), az);
            float s  = __fadd_rn(rxy2, __fmul_rn(rz, rz));
            if (s < Tocc) mO |= 1u << j;
            if (s < Tpro) mP |= 1u << j;
        }
        if (!mO) continue;

        int s0 = zs & 255;
        int w0 = s0 >> 5, off = s0 & 31;
        unsigned long long osh = ((unsigned long long)mO) << off;
        unsigned long long psh = ((unsigned long long)mP) << off;
        int colbase = ((cx & 255) << 8) | (cy & 255);
        unsigned long long v0 = ((unsigned long long)(unsigned)psh << 32)
                              |  (unsigned long long)(unsigned)osh;
        unsigned long long v1 = ((unsigned long long)(unsigned)(psh >> 32) << 32)
                              |  (unsigned long long)(unsigned)(osh >> 32);
        if (v0) atomicOr(&g_bits[(w0 << 16) + colbase], v0);
        if (v1) atomicOr(&g_bits[((((w0 + 1) & 7)) << 16) + colbase], v1);
    }
}

// ---- classify: solv = ds | (nb & ~prot), bitwise erosion ----
__global__ void classify_kernel() {
    __shared__ uint32_t sD0[8 * 400];
    __shared__ uint32_t sD1[8 * 400];
    __shared__ uint32_t sD2[8 * 400];
    int bx0 = (blockIdx.x & 15) * 16;
    int by0 = (blockIdx.x >> 4) * 16;
    int t = threadIdx.x;

    for (int c = t; c < 400; c += 256) {
        int lx = c % 20, ly = c / 20;
        int gx = (bx0 + lx - 2) & 255;
        int gy = (by0 + ly - 2) & 255;
        int col = (gx << 8) | gy;
        uint32_t ds[8], d1[8], d2[8];
        #pragma unroll
        for (int i = 0; i < 8; i++)
            ds[i] = ~(uint32_t)g_bits[(i << 16) + col];
        #pragma unroll
        for (int i = 0; i < 8; i++)
            d1[i] = ds[i] | (ds[i] << 1) | (ds[(i+7)&7] >> 31)
                          | (ds[i] >> 1) | (ds[(i+1)&7] << 31);
        #pragma unroll
        for (int i = 0; i < 8; i++)
            d2[i] = d1[i] | (d1[i] << 1) | (d1[(i+7)&7] >> 31)
                          | (d1[i] >> 1) | (d1[(i+1)&7] << 31);
        #pragma unroll
        for (int i = 0; i < 8; i++) {
            sD0[i*400 + c] = ds[i];
            sD1[i*400 + c] = d1[i];
            sD2[i*400 + c] = d2[i];
        }
    }
    __syncthreads();

    int lx = (t & 15) + 2, ly = (t >> 4) + 2;
    int gx = (bx0 + lx - 2) & 255;
    int gy = (by0 + ly - 2) & 255;
    int col = (gx << 8) | gy;
    int cc = ly * 20 + lx;
    #pragma unroll
    for (int i = 0; i < 8; i++) {
        const uint32_t* D0 = sD0 + i * 400;
        const uint32_t* D1 = sD1 + i * 400;
        const uint32_t* D2 = sD2 + i * 400;
        uint32_t nb =
            D2[cc] | D2[cc+1]  | D2[cc-1]  | D2[cc+20] | D2[cc-20] |
            D1[cc+21] | D1[cc+19] | D1[cc-19] | D1[cc-21] |
            D1[cc+2]  | D1[cc-2]  | D1[cc+40] | D1[cc-40] |
            D0[cc+22] | D0[cc+18] | D0[cc-18] | D0[cc-22] |
            D0[cc+41] | D0[cc+39] | D0[cc-39] | D0[cc-41];
        uint32_t p = (uint32_t)(g_bits[(i << 16) + col] >> 32);
        g_solvb[(i << 16) + col] = D0[cc] | (nb & ~p);
    }
}

// ---- K1: fused z+y blur from smem-staged bits (all f32, all coalesced) ----
// p00=a0*a0, p01=a0*a1, p11=a1*a1 (products computed in f64 on host, cast).
// zblur is linear in bits: zb(im)+zb(ip) = zb(im^ip) + 2*zb(im&ip).
__global__ __launch_bounds__(512)
void blur_zy_kernel(float p00, float p01, float p11) {
    __shared__ uint32_t sBits[8][66];      // [word][y0-1 .. y0+64]
    __shared__ float4 sLc[64], sLe[64];
    int t  = threadIdx.x;
    int x  = blockIdx.x >> 2;
    int y0 = (blockIdx.x & 3) << 6;

    if (t < 128) {
        int grp = t >> 6, e = t & 63;
        float b0 = (float)( e       & 1), b1 = (float)((e >> 1) & 1);
        float b2 = (float)((e >> 2) & 1), b3 = (float)((e >> 3) & 1);
        float b4 = (float)((e >> 4) & 1), b5 = (float)((e >> 5) & 1);
        float we = grp ? p11 : p01;        // z-edge coeff * (y scale)
        float wc = grp ? p01 : p00;        // z-center coeff * (y scale)
        float4 v = make_float4(
            fmaf(we, b0, fmaf(wc, b1, we * b2)),
            fmaf(we, b1, fmaf(wc, b2, we * b3)),
            fmaf(we, b2, fmaf(wc, b3, we * b4)),
            fmaf(we, b3, fmaf(wc, b4, we * b5)));
        if (grp == 0) sLc[e] = v; else sLe[e] = v;
    }
    for (int c = t; c < 528; c += 512) {
        int w = c / 66, yy = c % 66;
        int gy = (y0 + yy - 1) & 255;
        sBits[w][yy] = g_solvb[(w << 16) | (x << 8) | gy];
    }
    __syncthreads();

    int zg = t & 63;
    int zm = ((zg << 2) - 1) & 255;
    int wA = zm >> 5, wB = (wA + 1) & 7, off = zm & 31;
    int yb = t >> 6;                        // 0..7
    float4* outp = reinterpret_cast<float4*>(g_fA);
    #pragma unroll
    for (int j = 0; j < 8; ++j) {
        int yl = (j << 3) + yb;             // 0..63
        uint32_t ic = __funnelshift_r(sBits[wA][yl+1], sBits[wB][yl+1], off) & 63;
        uint32_t im = __funnelshift_r(sBits[wA][yl  ], sBits[wB][yl  ], off) & 63;
        uint32_t ip = __funnelshift_r(sBits[wA][yl+2], sBits[wB][yl+2], off) & 63;
        uint32_t e0 = im ^ ip, e1 = im & ip;
        float4 o  = sLc[ic];
        float4 l0 = sLe[e0];
        float4 l1 = sLe[e1];
        o.x = fmaf(2.0f, l1.x, o.x + l0.x);
        o.y = fmaf(2.0f, l1.y, o.y + l0.y);
        o.z = fmaf(2.0f, l1.z, o.z + l0.z);
        o.w = fmaf(2.0f, l1.w, o.w + l0.w);
        outp[(x << 14) | ((y0 + yl) << 6) | zg] = o;
    }
}

// ---- K2: x pass, rolling 3-window, 8 x-cells per thread ----
__global__ __launch_bounds__(256)
void blur_x_kernel(float4* __restrict__ out, float a0, float a1) {
    int cid = blockIdx.x * 256 + threadIdx.x;    // 524288 threads
    int xc  = cid >> 14;                         // 32 x-chunks of 8
    int yz  = cid & 16383;                       // (y<<6)|zgroup
    const float4* A = reinterpret_cast<const float4*>(g_fA);

    int x0 = xc << 3;
    float4 m = A[((((x0 + 255) & 255) << 14) | yz)];
    float4 c = A[((x0 << 14) | yz)];
    #pragma unroll
    for (int j = 0; j < 8; ++j) {
        int xn = (x0 + j + 1) & 255;
        float4 p = A[((xn << 14) | yz)];
        float4 o;
        o.x = fmaf(a1, m.x + p.x, a0 * c.x);
        o.y = fmaf(a1, m.y + p.y, a0 * c.y);
        o.z = fmaf(a1, m.z + p.z, a0 * c.z);
        o.w = fmaf(a1, m.w + p.w, a0 * c.w);
        out[(((x0 + j) << 14) | yz)] = o;
        m = c; c = p;
    }
}

extern "C" void kernel_launch(void* const* d_in, const int* in_sizes, int n_in,
                              void* d_out, int out_size) {
    const float* xyz = (const float*)d_in[0];
    const float* vdw = (const float*)d_in[1];
    int n_atoms = in_sizes[1];

    // all double math on the HOST; device sees only f32
    double sigma = 1.1 / (100.0 / 256.0) / 4.0;
    double w = exp(-1.0 / (2.0 * sigma * sigma));
    double s = 1.0 + 2.0 * w;
    double a0d = 1.0 / s, a1d = w / s;
    float p00 = (float)(a0d * a0d);
    float p01 = (float)(a0d * a1d);
    float p11 = (float)(a1d * a1d);

    zero_kernel     <<<1024, 256>>>();
    splat_kernel    <<<(n_atoms + 3) / 4, 128>>>(xyz, vdw, n_atoms);
    classify_kernel <<<256, 256>>>();
    blur_zy_kernel  <<<1024, 512>>>(p00, p01, p11);
    blur_x_kernel   <<<2048, 256>>>((float4*)d_out, (float)a0d, (float)a1d);
}

// round 6
// speedup vs baseline: 2.4116x; 1.0026x over previous
#include <cuda_runtime.h>
#include <math.h>
#include <stdint.h>

#define NG   256
#define NG3  16777216
#define NW   (NG3/32)           // 524288 z-words per mask
#define SP   0.390625f          // 100/256, exact in f32

// combined grid: per z-word, lo32 = occ bits, hi32 = prot bits
static __device__ unsigned long long g_bits[NW];
static __device__ uint32_t           g_solvb[NW];

// ---- zero the splat grid (4 MB) ----
__global__ void zero_kernel() {
    unsigned i = blockIdx.x * blockDim.x + threadIdx.x;
    if (i < NW / 2)
        reinterpret_cast<uint4*>(g_bits)[i] = make_uint4(0u, 0u, 0u, 0u);
}

// smallest float T with (s < T) <=> (sqrt_rn(s) < R)
__device__ __forceinline__ float cut_threshold(float R) {
    float t = __fmul_rn(R, R);
    while (__fsqrt_rn(t) >= R)
        t = __uint_as_float(__float_as_uint(t) - 1u);
    while (__fsqrt_rn(__uint_as_float(__float_as_uint(t) + 1u)) < R)
        t = __uint_as_float(__float_as_uint(t) + 1u);
    return __uint_as_float(__float_as_uint(t) + 1u);
}

// ---- splat: one warp per atom, branch-free 17-cell mask per (dx,dy) ----
__global__ void splat_kernel(const float* __restrict__ xyz,
                             const float* __restrict__ vdw,
                             int n_atoms) {
    int a = blockIdx.x * 4 + (threadIdx.x >> 5);
    if (a >= n_atoms) return;
    int lane = threadIdx.x & 31;
    float ax = xyz[3*a], ay = xyz[3*a+1], az = xyz[3*a+2];
    float vr = vdw[a];
    float R    = __fadd_rn(vr, 1.1f);
    float Tocc = cut_threshold(R);
    float Tpro = cut_threshold(vr);

    int bx = (int)floorf(__fdiv_rn(ax, SP));
    int by = (int)floorf(__fdiv_rn(ay, SP));
    int bz = (int)floorf(__fdiv_rn(az, SP));
    int zs = bz - 8;

    for (int p = lane; p < 289; p += 32) {
        int dx = p / 17 - 8;
        int dy = p % 17 - 8;
        int cx = bx + dx, cy = by + dy;
        float rx = __fsub_rn(__fmul_rn((float)cx, SP), ax);
        float ry = __fsub_rn(__fmul_rn((float)cy, SP), ay);
        float rxy2 = __fadd_rn(__fmul_rn(rx, rx), __fmul_rn(ry, ry));
        if (rxy2 >= Tocc) continue;           // exact: s >= rxy2

        unsigned mO = 0, mP = 0;
        #pragma unroll
        for (int j = 0; j < 17; ++j) {        // exact ref predicate per cell
            float rz = __fsub_rn(__fmul_rn((float)(zs + j), SP), az);
            float s  = __fadd_rn(rxy2, __fmul_rn(rz, rz));
            if (s < Tocc) mO |= 1u << j;
            if (s < Tpro) mP |= 1u << j;
        }
        if (!mO) continue;

        int s0 = zs & 255;
        int w0 = s0 >> 5, off = s0 & 31;
        unsigned long long osh = ((unsigned long long)mO) << off;
        unsigned long long psh = ((unsigned long long)mP) << off;
        int colbase = ((cx & 255) << 8) | (cy & 255);
        unsigned long long v0 = ((unsigned long long)(unsigned)psh << 32)
                              |  (unsigned long long)(unsigned)osh;
        unsigned long long v1 = ((unsigned long long)(unsigned)(psh >> 32) << 32)
                              |  (unsigned long long)(unsigned)(osh >> 32);
        if (v0) atomicOr(&g_bits[(w0 << 16) + colbase], v0);
        if (v1) atomicOr(&g_bits[((((w0 + 1) & 7)) << 16) + colbase], v1);
    }
}

// ---- classify: solv = ds | (nb & ~prot), bitwise erosion ----
__global__ void classify_kernel() {
    __shared__ uint32_t sD0[8 * 400];
    __shared__ uint32_t sD1[8 * 400];
    __shared__ uint32_t sD2[8 * 400];
    int bx0 = (blockIdx.x & 15) * 16;
    int by0 = (blockIdx.x >> 4) * 16;
    int t = threadIdx.x;

    for (int c = t; c < 400; c += 256) {
        int lx = c % 20, ly = c / 20;
        int gx = (bx0 + lx - 2) & 255;
        int gy = (by0 + ly - 2) & 255;
        int col = (gx << 8) | gy;
        uint32_t ds[8], d1[8], d2[8];
        #pragma unroll
        for (int i = 0; i < 8; i++)
            ds[i] = ~(uint32_t)g_bits[(i << 16) + col];
        #pragma unroll
        for (int i = 0; i < 8; i++)
            d1[i] = ds[i] | (ds[i] << 1) | (ds[(i+7)&7] >> 31)
                          | (ds[i] >> 1) | (ds[(i+1)&7] << 31);
        #pragma unroll
        for (int i = 0; i < 8; i++)
            d2[i] = d1[i] | (d1[i] << 1) | (d1[(i+7)&7] >> 31)
                          | (d1[i] >> 1) | (d1[(i+1)&7] << 31);
        #pragma unroll
        for (int i = 0; i < 8; i++) {
            sD0[i*400 + c] = ds[i];
            sD1[i*400 + c] = d1[i];
            sD2[i*400 + c] = d2[i];
        }
    }
    __syncthreads();

    int lx = (t & 15) + 2, ly = (t >> 4) + 2;
    int gx = (bx0 + lx - 2) & 255;
    int gy = (by0 + ly - 2) & 255;
    int col = (gx << 8) | gy;
    int cc = ly * 20 + lx;
    #pragma unroll
    for (int i = 0; i < 8; i++) {
        const uint32_t* D0 = sD0 + i * 400;
        const uint32_t* D1 = sD1 + i * 400;
        const uint32_t* D2 = sD2 + i * 400;
        uint32_t nb =
            D2[cc] | D2[cc+1]  | D2[cc-1]  | D2[cc+20] | D2[cc-20] |
            D1[cc+21] | D1[cc+19] | D1[cc-19] | D1[cc-21] |
            D1[cc+2]  | D1[cc-2]  | D1[cc+40] | D1[cc-40] |
            D0[cc+22] | D0[cc+18] | D0[cc-18] | D0[cc-22] |
            D0[cc+41] | D0[cc+39] | D0[cc-39] | D0[cc-41];
        uint32_t p = (uint32_t)(g_bits[(i << 16) + col] >> 32);
        g_solvb[(i << 16) + col] = D0[cc] | (nb & ~p);
    }
}

// ---- fused 27-tap blur, bits -> d_out, single pass ----
// zb() (z-blur of a 6-bit window) is linear in bits, so:
//   sum over 4 edge cols  = zb(E0) + 2 zb(E1) + 4 zb(E2)   (bitwise CSA)
//   sum over 4 corner cols= zb(K0) + 2 zb(K1) + 4 zb(K2)
// out = p00*zb(C) + p01*(edges) + p11*(corners)
__global__ __launch_bounds__(512)
void blur_fused_kernel(float4* __restrict__ out,
                       float p00, float p01, float p11, float wsum) {
    __shared__ uint32_t sBits[66][3][10];   // [y0-1..y0+64][x-1..x+1][word0..7,dup0,pad]
    __shared__ float4 sLz[64];
    int t  = threadIdx.x;
    int x  = blockIdx.x >> 2;
    int y0 = (blockIdx.x & 3) << 6;

    if (t < 64) {
        // unscaled z-profile LUT (a1,a0,a1 taps); scales applied per group
        float b0 = (float)( t       & 1), b1 = (float)((t >> 1) & 1);
        float b2 = (float)((t >> 2) & 1), b3 = (float)((t >> 3) & 1);
        float b4 = (float)((t >> 4) & 1), b5 = (float)((t >> 5) & 1);
        const float A0 = 0.51285326f;   // placeholder overwritten below via params
        (void)A0;
        // a0,a1 recovered from p00,p01: a0 = p00/sqrt? -- instead pass via wsum trick:
        // we embed a0,a1 in p-group products only; build LUT with a-taps:
        // a1 = p01/ (p00/a0) ... simpler: host passes a0,a1 packed in wsum? no.
        sLz[t] = make_float4(0,0,0,0);  // filled right below with a-taps
        // NOTE: actual fill happens in the second if-block using __a0/__a1 params
    }
    __syncthreads();
    // real LUT fill (a0 = p00/ß, need direct values) -- use constant reconstruction:
    // a0 and a1 satisfy p00 = a0*a0, p01 = a0*a1. So a0 = sqrtf(p00), a1 = p01/a0.
    if (t < 64) {
        float a0 = __fsqrt_rn(p00);
        float a1 = __fdividef(p01, a0);
        float b0 = (float)( t       & 1), b1 = (float)((t >> 1) & 1);
        float b2 = (float)((t >> 2) & 1), b3 = (float)((t >> 3) & 1);
        float b4 = (float)((t >> 4) & 1), b5 = (float)((t >> 5) & 1);
        sLz[t] = make_float4(
            fmaf(a1, b0, fmaf(a0, b1, a1 * b2)),
            fmaf(a1, b1, fmaf(a0, b2, a1 * b3)),
            fmaf(a1, b2, fmaf(a0, b3, a1 * b4)),
            fmaf(a1, b3, fmaf(a0, b4, a1 * b5)));
    }
    for (int c = t; c < 1584; c += 512) {
        int pw = c / 66, yy = c % 66;            // consecutive threads -> consecutive gy
        int p = pw >> 3, w = pw & 7;
        int gx = (x + p - 1) & 255;
        int gy = (y0 + yy - 1) & 255;
        uint32_t v = g_solvb[(w << 16) | (gx << 8) | gy];
        sBits[yy][p][w] = v;
        if (w == 0) sBits[yy][p][8] = v;         // wrap duplicate for word-pair reads
    }
    __syncthreads();

    int zg = t & 63;
    int yb = t >> 6;
    int zm = ((zg << 2) - 1) & 255;
    int wA = zm >> 5, off = zm & 31;

    #pragma unroll
    for (int j = 0; j < 8; ++j) {
        int yl = (j << 3) + yb;                  // 0..63
        uint32_t W[3][3];
        #pragma unroll
        for (int p = 0; p < 3; ++p) {
            #pragma unroll
            for (int q = 0; q < 3; ++q) {
                const uint32_t* base = &sBits[yl + q][p][0];
                W[p][q] = __funnelshift_r(base[wA], base[wA + 1], off) & 63u;
            }
        }
        uint32_t morr = W[0][0]|W[0][1]|W[0][2]|W[1][0]|W[1][1]|W[1][2]
                       |W[2][0]|W[2][1]|W[2][2];
        uint32_t mand = W[0][0]&W[0][1]&W[0][2]&W[1][0]&W[1][1]&W[1][2]
                       &W[2][0]&W[2][1]&W[2][2];
        int oidx = (x << 14) | ((y0 + yl) << 6) | zg;

        if (__all_sync(0xffffffffu, morr == 0u)) {
            out[oidx] = make_float4(0.f, 0.f, 0.f, 0.f);
        } else if (__all_sync(0xffffffffu, mand == 63u)) {
            out[oidx] = make_float4(wsum, wsum, wsum, wsum);
        } else {
            uint32_t E0, E1, E2, K0, K1, K2;
            {   uint32_t u = W[0][1] ^ W[2][1], v = W[0][1] & W[2][1];
                uint32_t s2 = W[1][0] ^ W[1][2], c2 = W[1][0] & W[1][2];
                E0 = u ^ s2; uint32_t c3 = u & s2;
                E1 = v ^ c2 ^ c3;
                E2 = (v & c2) | (c3 & (v | c2)); }
            {   uint32_t u = W[0][0] ^ W[0][2], v = W[0][0] & W[0][2];
                uint32_t s2 = W[2][0] ^ W[2][2], c2 = W[2][0] & W[2][2];
                K0 = u ^ s2; uint32_t c3 = u & s2;
                K1 = v ^ c2 ^ c3;
                K2 = (v & c2) | (c3 & (v | c2)); }
            float4 Lc  = sLz[W[1][1]];
            float4 le0 = sLz[E0], le1 = sLz[E1], le2 = sLz[E2];
            float4 lk0 = sLz[K0], lk1 = sLz[K1], lk2 = sLz[K2];
            float4 o;
            float e, k;
            e = fmaf(2.f, le1.x, le0.x); e = fmaf(4.f, le2.x, e);
            k = fmaf(2.f, lk1.x, lk0.x); k = fmaf(4.f, lk2.x, k);
            o.x = fmaf(p11, k, fmaf(p01, e, p00 * Lc.x));
            e = fmaf(2.f, le1.y, le0.y); e = fmaf(4.f, le2.y, e);
            k = fmaf(2.f, lk1.y, lk0.y); k = fmaf(4.f, lk2.y, k);
            o.y = fmaf(p11, k, fmaf(p01, e, p00 * Lc.y));
            e = fmaf(2.f, le1.z, le0.z); e = fmaf(4.f, le2.z, e);
            k = fmaf(2.f, lk1.z, lk0.z); k = fmaf(4.f, lk2.z, k);
            o.z = fmaf(p11, k, fmaf(p01, e, p00 * Lc.z));
            e = fmaf(2.f, le1.w, le0.w); e = fmaf(4.f, le2.w, e);
            k = fmaf(2.f, lk1.w, lk0.w); k = fmaf(4.f, lk2.w, k);
            o.w = fmaf(p11, k, fmaf(p01, e, p00 * Lc.w));
            out[oidx] = o;
        }
    }
}

extern "C" void kernel_launch(void* const* d_in, const int* in_sizes, int n_in,
                              void* d_out, int out_size) {
    const float* xyz = (const float*)d_in[0];
    const float* vdw = (const float*)d_in[1];
    int n_atoms = in_sizes[1];

    // all double math on the HOST; device sees only f32
    double sigma = 1.1 / (100.0 / 256.0) / 4.0;
    double w = exp(-1.0 / (2.0 * sigma * sigma));
    double s = 1.0 + 2.0 * w;
    double a0d = 1.0 / s, a1d = w / s;
    float p00 = (float)(a0d * a0d);
    float p01 = (float)(a0d * a1d);
    float p11 = (float)(a1d * a1d);
    double t3 = a0d + 2.0 * a1d;
    float wsum = (float)(t3 * t3 * t3);

    zero_kernel      <<<1024, 256>>>();
    splat_kernel     <<<(n_atoms + 3) / 4, 128>>>(xyz, vdw, n_atoms);
    classify_kernel  <<<256, 256>>>();
    blur_fused_kernel<<<1024, 512>>>((float4*)d_out, p00, p01, p11, wsum);
}

// round 7
// speedup vs baseline: 2.7387x; 1.1357x over previous
#include <cuda_runtime.h>
#include <math.h>
#include <stdint.h>

#define NG   256
#define NG3  16777216
#define NW   (NG3/32)           // 524288 z-words per mask
#define SP   0.390625f          // 100/256, exact in f32

// combined grid: per z-word, lo32 = occ bits, hi32 = prot bits
static __device__ unsigned long long g_bits[NW];
static __device__ uint32_t           g_solvb[NW];

// ---- zero the splat grid (4 MB) ----
__global__ void zero_kernel() {
    unsigned i = blockIdx.x * blockDim.x + threadIdx.x;
    if (i < NW / 2)
        reinterpret_cast<uint4*>(g_bits)[i] = make_uint4(0u, 0u, 0u, 0u);
}

// smallest float T with (s < T) <=> (sqrt_rn(s) < R)
__device__ __forceinline__ float cut_threshold(float R) {
    float t = __fmul_rn(R, R);
    while (__fsqrt_rn(t) >= R)
        t = __uint_as_float(__float_as_uint(t) - 1u);
    while (__fsqrt_rn(__uint_as_float(__float_as_uint(t) + 1u)) < R)
        t = __uint_as_float(__float_as_uint(t) + 1u);
    return __uint_as_float(__float_as_uint(t) + 1u);
}

// ---- splat: one warp per atom, branch-free 17-cell mask per (dx,dy) ----
__global__ void splat_kernel(const float* __restrict__ xyz,
                             const float* __restrict__ vdw,
                             int n_atoms) {
    int a = blockIdx.x * 4 + (threadIdx.x >> 5);
    if (a >= n_atoms) return;
    int lane = threadIdx.x & 31;
    float ax = xyz[3*a], ay = xyz[3*a+1], az = xyz[3*a+2];
    float vr = vdw[a];
    float R    = __fadd_rn(vr, 1.1f);
    float Tocc = cut_threshold(R);
    float Tpro = cut_threshold(vr);

    int bx = (int)floorf(__fdiv_rn(ax, SP));
    int by = (int)floorf(__fdiv_rn(ay, SP));
    int bz = (int)floorf(__fdiv_rn(az, SP));
    int zs = bz - 8;

    for (int p = lane; p < 289; p += 32) {
        int dx = p / 17 - 8;
        int dy = p % 17 - 8;
        int cx = bx + dx, cy = by + dy;
        float rx = __fsub_rn(__fmul_rn((float)cx, SP), ax);
        float ry = __fsub_rn(__fmul_rn((float)cy, SP), ay);
        float rxy2 = __fadd_rn(__fmul_rn(rx, rx), __fmul_rn(ry, ry));
        if (rxy2 >= Tocc) continue;           // exact: s >= rxy2

        unsigned mO = 0, mP = 0;
        #pragma unroll
        for (int j = 0; j < 17; ++j) {        // exact ref predicate per cell
            float rz = __fsub_rn(__fmul_rn((float)(zs + j), SP), az);
            float s  = __fadd_rn(rxy2, __fmul_rn(rz, rz));
            if (s < Tocc) mO |= 1u << j;
            if (s < Tpro) mP |= 1u << j;
        }
        if (!mO) continue;

        int s0 = zs & 255;
        int w0 = s0 >> 5, off = s0 & 31;
        unsigned long long osh = ((unsigned long long)mO) << off;
        unsigned long long psh = ((unsigned long long)mP) << off;
        int colbase = ((cx & 255) << 8) | (cy & 255);
        unsigned long long v0 = ((unsigned long long)(unsigned)psh << 32)
                              |  (unsigned long long)(unsigned)osh;
        unsigned long long v1 = ((unsigned long long)(unsigned)(psh >> 32) << 32)
                              |  (unsigned long long)(unsigned)(osh >> 32);
        if (v0) atomicOr(&g_bits[(w0 << 16) + colbase], v0);
        if (v1) atomicOr(&g_bits[((((w0 + 1) & 7)) << 16) + colbase], v1);
    }
}

// ---- classify: solv = ds | (nb & ~prot), bitwise erosion ----
__global__ void classify_kernel() {
    __shared__ uint32_t sD0[8 * 400];
    __shared__ uint32_t sD1[8 * 400];
    __shared__ uint32_t sD2[8 * 400];
    int bx0 = (blockIdx.x & 15) * 16;
    int by0 = (blockIdx.x >> 4) * 16;
    int t = threadIdx.x;

    for (int c = t; c < 400; c += 256) {
        int lx = c % 20, ly = c / 20;
        int gx = (bx0 + lx - 2) & 255;
        int gy = (by0 + ly - 2) & 255;
        int col = (gx << 8) | gy;
        uint32_t ds[8], d1[8], d2[8];
        #pragma unroll
        for (int i = 0; i < 8; i++)
            ds[i] = ~(uint32_t)g_bits[(i << 16) + col];
        #pragma unroll
        for (int i = 0; i < 8; i++)
            d1[i] = ds[i] | (ds[i] << 1) | (ds[(i+7)&7] >> 31)
                          | (ds[i] >> 1) | (ds[(i+1)&7] << 31);
        #pragma unroll
        for (int i = 0; i < 8; i++)
            d2[i] = d1[i] | (d1[i] << 1) | (d1[(i+7)&7] >> 31)
                          | (d1[i] >> 1) | (d1[(i+1)&7] << 31);
        #pragma unroll
        for (int i = 0; i < 8; i++) {
            sD0[i*400 + c] = ds[i];
            sD1[i*400 + c] = d1[i];
            sD2[i*400 + c] = d2[i];
        }
    }
    __syncthreads();

    int lx = (t & 15) + 2, ly = (t >> 4) + 2;
    int gx = (bx0 + lx - 2) & 255;
    int gy = (by0 + ly - 2) & 255;
    int col = (gx << 8) | gy;
    int cc = ly * 20 + lx;
    #pragma unroll
    for (int i = 0; i < 8; i++) {
        const uint32_t* D0 = sD0 + i * 400;
        const uint32_t* D1 = sD1 + i * 400;
        const uint32_t* D2 = sD2 + i * 400;
        uint32_t nb =
            D2[cc] | D2[cc+1]  | D2[cc-1]  | D2[cc+20] | D2[cc-20] |
            D1[cc+21] | D1[cc+19] | D1[cc-19] | D1[cc-21] |
            D1[cc+2]  | D1[cc-2]  | D1[cc+40] | D1[cc-40] |
            D0[cc+22] | D0[cc+18] | D0[cc-18] | D0[cc-22] |
            D0[cc+41] | D0[cc+39] | D0[cc-39] | D0[cc-41];
        uint32_t p = (uint32_t)(g_bits[(i << 16) + col] >> 32);
        g_solvb[(i << 16) + col] = D0[cc] | (nb & ~p);
    }
}

// CSA of 4 one-bit vectors: sum = lo + 2*mid + 4*hi
__device__ __forceinline__ void csa4(uint32_t a, uint32_t b, uint32_t c, uint32_t d,
                                     uint32_t& lo, uint32_t& mid, uint32_t& hi) {
    uint32_t s1 = a ^ b ^ c;
    uint32_t m1 = (a & b) | (c & (a | b));
    uint32_t cy = s1 & d;
    lo  = s1 ^ d;
    mid = m1 ^ cy;
    hi  = m1 & cy;
}

// ---- fused 27-tap blur v2: register CSA planes per 32-z word ----
// thread = (y, word); planes amortized over 8 float4 outputs.
__global__ __launch_bounds__(256)
void blur_fused2_kernel(float4* __restrict__ out,
                        float a0, float a1,
                        float p00, float p01, float p11, float wsum) {
    __shared__ uint32_t sB[34][3][8];     // [y0-1..y0+32][x-1..x+1][word]
    __shared__ float4   sLz[64];          // z-profile LUT (unscaled taps a1,a0,a1)
    __shared__ float4   sOut[2048];       // transpose buffer, swizzled

    int t  = threadIdx.x;
    int x  = blockIdx.x >> 3;
    int y0 = (blockIdx.x & 7) << 5;

    if (t < 64) {
        float b0 = (float)( t       & 1), b1 = (float)((t >> 1) & 1);
        float b2 = (float)((t >> 2) & 1), b3 = (float)((t >> 3) & 1);
        float b4 = (float)((t >> 4) & 1), b5 = (float)((t >> 5) & 1);
        sLz[t] = make_float4(
            fmaf(a1, b0, fmaf(a0, b1, a1 * b2)),
            fmaf(a1, b1, fmaf(a0, b2, a1 * b3)),
            fmaf(a1, b2, fmaf(a0, b3, a1 * b4)),
            fmaf(a1, b3, fmaf(a0, b4, a1 * b5)));
    }
    for (int c = t; c < 816; c += 256) {           // 8 words * 3 x * 34 y
        int w  = c / 102;
        int r  = c % 102;
        int xi = r / 34, yy = r % 34;
        int gx = (x + xi - 1) & 255;
        int gy = (y0 + yy - 1) & 255;
        sB[yy][xi][w] = g_solvb[(w << 16) | (gx << 8) | gy];
    }
    __syncthreads();

    int yl = t >> 3;          // 0..31
    int w  = t & 7;           // word
    int wm = (w + 7) & 7, wp = (w + 1) & 7;

    uint32_t C[3], E0[3], E1[3], E2[3], K0[3], K1[3], K2[3];
    #pragma unroll
    for (int k = 0; k < 3; k++) {
        int wk = (k == 0) ? wm : (k == 1) ? w : wp;
        uint32_t cc = sB[yl+1][1][wk];
        uint32_t ea = sB[yl+1][0][wk], eb = sB[yl+1][2][wk];
        uint32_t ec = sB[yl  ][1][wk], ed = sB[yl+2][1][wk];
        uint32_t ka = sB[yl  ][0][wk], kb = sB[yl  ][2][wk];
        uint32_t kc = sB[yl+2][0][wk], kd = sB[yl+2][2][wk];
        C[k] = cc;
        csa4(ea, eb, ec, ed, E0[k], E1[k], E2[k]);
        csa4(ka, kb, kc, kd, K0[k], K1[k], K2[k]);
    }

    #pragma unroll
    for (int j = 0; j < 8; j++) {
        uint32_t wC, w0e, w1e, w2e, w0k, w1k, w2k;
        if (j == 0) {
            wC  = __funnelshift_r(C [0], C [1], 31) & 63u;
            w0e = __funnelshift_r(E0[0], E0[1], 31) & 63u;
            w1e = __funnelshift_r(E1[0], E1[1], 31) & 63u;
            w2e = __funnelshift_r(E2[0], E2[1], 31) & 63u;
            w0k = __funnelshift_r(K0[0], K0[1], 31) & 63u;
            w1k = __funnelshift_r(K1[0], K1[1], 31) & 63u;
            w2k = __funnelshift_r(K2[0], K2[1], 31) & 63u;
        } else {
            int sh = 4 * j - 1;
            wC  = __funnelshift_r(C [1], C [2], sh) & 63u;
            w0e = __funnelshift_r(E0[1], E0[2], sh) & 63u;
            w1e = __funnelshift_r(E1[1], E1[2], sh) & 63u;
            w2e = __funnelshift_r(E2[1], E2[2], sh) & 63u;
            w0k = __funnelshift_r(K0[1], K0[2], sh) & 63u;
            w1k = __funnelshift_r(K1[1], K1[2], sh) & 63u;
            w2k = __funnelshift_r(K2[1], K2[2], sh) & 63u;
        }

        float4 o;
        uint32_t anyb = wC | w0e | w1e | w2e | w0k | w1k | w2k;
        if (anyb == 0u) {
            o = make_float4(0.f, 0.f, 0.f, 0.f);
        } else if ((wC & w2e & w2k) == 63u && (w0e | w1e | w0k | w1k) == 0u) {
            o = make_float4(wsum, wsum, wsum, wsum);
        } else {
            float4 Lc  = sLz[wC];
            float4 le0 = sLz[w0e], le1 = sLz[w1e], le2 = sLz[w2e];
            float4 lk0 = sLz[w0k], lk1 = sLz[w1k], lk2 = sLz[w2k];
            float e, k;
            e = fmaf(2.f, le1.x, le0.x); e = fmaf(4.f, le2.x, e);
            k = fmaf(2.f, lk1.x, lk0.x); k = fmaf(4.f, lk2.x, k);
            o.x = fmaf(p11, k, fmaf(p01, e, p00 * Lc.x));
            e = fmaf(2.f, le1.y, le0.y); e = fmaf(4.f, le2.y, e);
            k = fmaf(2.f, lk1.y, lk0.y); k = fmaf(4.f, lk2.y, k);
            o.y = fmaf(p11, k, fmaf(p01, e, p00 * Lc.y));
            e = fmaf(2.f, le1.z, le0.z); e = fmaf(4.f, le2.z, e);
            k = fmaf(2.f, lk1.z, lk0.z); k = fmaf(4.f, lk2.z, k);
            o.z = fmaf(p11, k, fmaf(p01, e, p00 * Lc.z));
            e = fmaf(2.f, le1.w, le0.w); e = fmaf(4.f, le2.w, e);
            k = fmaf(2.f, lk1.w, lk0.w); k = fmaf(4.f, lk2.w, k);
            o.w = fmaf(p11, k, fmaf(p01, e, p00 * Lc.w));
        }
        // swizzled transpose slot: zg = 8w + j -> idx = zg ^ w (bank-safe both phases)
        sOut[(yl << 6) + (w << 3) + (j ^ w)] = o;
    }
    __syncthreads();

    #pragma unroll
    for (int k2 = 0; k2 < 8; k2++) {
        int flat = (k2 << 8) + t;
        int yy2 = flat >> 6;
        int zg2 = flat & 63;
        float4 v = sOut[(yy2 << 6) + (zg2 ^ (zg2 >> 3))];
        out[(x << 14) | ((y0 + yy2) << 6) | zg2] = v;
    }
}

extern "C" void kernel_launch(void* const* d_in, const int* in_sizes, int n_in,
                              void* d_out, int out_size) {
    const float* xyz = (const float*)d_in[0];
    const float* vdw = (const float*)d_in[1];
    int n_atoms = in_sizes[1];

    // all double math on the HOST; device sees only f32
    double sigma = 1.1 / (100.0 / 256.0) / 4.0;
    double w = exp(-1.0 / (2.0 * sigma * sigma));
    double s = 1.0 + 2.0 * w;
    double a0d = 1.0 / s, a1d = w / s;
    float a0  = (float)a0d;
    float a1  = (float)a1d;
    float p00 = (float)(a0d * a0d);
    float p01 = (float)(a0d * a1d);
    float p11 = (float)(a1d * a1d);
    double t3 = a0d + 2.0 * a1d;
    float wsum = (float)(t3 * t3 * t3);

    zero_kernel       <<<1024, 256>>>();
    splat_kernel      <<<(n_atoms + 3) / 4, 128>>>(xyz, vdw, n_atoms);
    classify_kernel   <<<256, 256>>>();
    blur_fused2_kernel<<<2048, 256>>>((float4*)d_out, a0, a1, p00, p01, p11, wsum);
}

// round 8
// speedup vs baseline: 3.0882x; 1.1276x over previous
#include <cuda_runtime.h>
#include <math.h>
#include <stdint.h>

#define NG   256
#define NG3  16777216
#define NW   (NG3/32)           // 524288 z-words per mask
#define SP   0.390625f          // 100/256, exact in f32

// combined grid: per z-word, lo32 = occ bits, hi32 = prot bits
static __device__ unsigned long long g_bits[NW];
static __device__ uint32_t           g_solvb[NW];

// ---- zero the splat grid (4 MB) ----
__global__ void zero_kernel() {
    unsigned i = blockIdx.x * blockDim.x + threadIdx.x;
    if (i < NW / 2)
        reinterpret_cast<uint4*>(g_bits)[i] = make_uint4(0u, 0u, 0u, 0u);
}

// smallest float T with (s < T) <=> (sqrt_rn(s) < R)
__device__ __forceinline__ float cut_threshold(float R) {
    float t = __fmul_rn(R, R);
    while (__fsqrt_rn(t) >= R)
        t = __uint_as_float(__float_as_uint(t) - 1u);
    while (__fsqrt_rn(__uint_as_float(__float_as_uint(t) + 1u)) < R)
        t = __uint_as_float(__float_as_uint(t) + 1u);
    return __uint_as_float(__float_as_uint(t) + 1u);
}

// ---- splat: one warp per atom, branch-free 17-cell mask per (dx,dy) ----
__global__ void splat_kernel(const float* __restrict__ xyz,
                             const float* __restrict__ vdw,
                             int n_atoms) {
    int a = blockIdx.x * 4 + (threadIdx.x >> 5);
    if (a >= n_atoms) return;
    int lane = threadIdx.x & 31;
    float ax = xyz[3*a], ay = xyz[3*a+1], az = xyz[3*a+2];
    float vr = vdw[a];
    float R    = __fadd_rn(vr, 1.1f);
    float Tocc = cut_threshold(R);
    float Tpro = cut_threshold(vr);

    int bx = (int)floorf(__fdiv_rn(ax, SP));
    int by = (int)floorf(__fdiv_rn(ay, SP));
    int bz = (int)floorf(__fdiv_rn(az, SP));
    int zs = bz - 8;

    for (int p = lane; p < 289; p += 32) {
        int dx = p / 17 - 8;
        int dy = p % 17 - 8;
        int cx = bx + dx, cy = by + dy;
        float rx = __fsub_rn(__fmul_rn((float)cx, SP), ax);
        float ry = __fsub_rn(__fmul_rn((float)cy, SP), ay);
        float rxy2 = __fadd_rn(__fmul_rn(rx, rx), __fmul_rn(ry, ry));
        if (rxy2 >= Tocc) continue;           // exact: s >= rxy2

        unsigned mO = 0, mP = 0;
        #pragma unroll
        for (int j = 0; j < 17; ++j) {        // exact ref predicate per cell
            float rz = __fsub_rn(__fmul_rn((float)(zs + j), SP), az);
            float s  = __fadd_rn(rxy2, __fmul_rn(rz, rz));
            if (s < Tocc) mO |= 1u << j;
            if (s < Tpro) mP |= 1u << j;
        }
        if (!mO) continue;

        int s0 = zs & 255;
        int w0 = s0 >> 5, off = s0 & 31;
        unsigned long long osh = ((unsigned long long)mO) << off;
        unsigned long long psh = ((unsigned long long)mP) << off;
        int colbase = ((cx & 255) << 8) | (cy & 255);
        unsigned long long v0 = ((unsigned long long)(unsigned)psh << 32)
                              |  (unsigned long long)(unsigned)osh;
        unsigned long long v1 = ((unsigned long long)(unsigned)(psh >> 32) << 32)
                              |  (unsigned long long)(unsigned)(osh >> 32);
        if (v0) atomicOr(&g_bits[(w0 << 16) + colbase], v0);
        if (v1) atomicOr(&g_bits[((((w0 + 1) & 7)) << 16) + colbase], v1);
    }
}

// ---- classify: solv = ds | (nb & ~prot), bitwise erosion ----
__global__ void classify_kernel() {
    __shared__ uint32_t sD0[8 * 400];
    __shared__ uint32_t sD1[8 * 400];
    __shared__ uint32_t sD2[8 * 400];
    int bx0 = (blockIdx.x & 15) * 16;
    int by0 = (blockIdx.x >> 4) * 16;
    int t = threadIdx.x;

    for (int c = t; c < 400; c += 256) {
        int lx = c % 20, ly = c / 20;
        int gx = (bx0 + lx - 2) & 255;
        int gy = (by0 + ly - 2) & 255;
        int col = (gx << 8) | gy;
        uint32_t ds[8], d1[8], d2[8];
        #pragma unroll
        for (int i = 0; i < 8; i++)
            ds[i] = ~(uint32_t)g_bits[(i << 16) + col];
        #pragma unroll
        for (int i = 0; i < 8; i++)
            d1[i] = ds[i] | (ds[i] << 1) | (ds[(i+7)&7] >> 31)
                          | (ds[i] >> 1) | (ds[(i+1)&7] << 31);
        #pragma unroll
        for (int i = 0; i < 8; i++)
            d2[i] = d1[i] | (d1[i] << 1) | (d1[(i+7)&7] >> 31)
                          | (d1[i] >> 1) | (d1[(i+1)&7] << 31);
        #pragma unroll
        for (int i = 0; i < 8; i++) {
            sD0[i*400 + c] = ds[i];
            sD1[i*400 + c] = d1[i];
            sD2[i*400 + c] = d2[i];
        }
    }
    __syncthreads();

    int lx = (t & 15) + 2, ly = (t >> 4) + 2;
    int gx = (bx0 + lx - 2) & 255;
    int gy = (by0 + ly - 2) & 255;
    int col = (gx << 8) | gy;
    int cc = ly * 20 + lx;
    #pragma unroll
    for (int i = 0; i < 8; i++) {
        const uint32_t* D0 = sD0 + i * 400;
        const uint32_t* D1 = sD1 + i * 400;
        const uint32_t* D2 = sD2 + i * 400;
        uint32_t nb =
            D2[cc] | D2[cc+1]  | D2[cc-1]  | D2[cc+20] | D2[cc-20] |
            D1[cc+21] | D1[cc+19] | D1[cc-19] | D1[cc-21] |
            D1[cc+2]  | D1[cc-2]  | D1[cc+40] | D1[cc-40] |
            D0[cc+22] | D0[cc+18] | D0[cc-18] | D0[cc-22] |
            D0[cc+41] | D0[cc+39] | D0[cc-39] | D0[cc-41];
        uint32_t p = (uint32_t)(g_bits[(i << 16) + col] >> 32);
        g_solvb[(i << 16) + col] = D0[cc] | (nb & ~p);
    }
}

// CSA of 4 one-bit vectors: sum = lo + 2*mid + 4*hi
__device__ __forceinline__ void csa4(uint32_t a, uint32_t b, uint32_t c, uint32_t d,
                                     uint32_t& lo, uint32_t& mid, uint32_t& hi) {
    uint32_t s1 = a ^ b ^ c;
    uint32_t m1 = (a & b) | (c & (a | b));
    uint32_t cy = s1 & d;
    lo  = s1 ^ d;
    mid = m1 ^ cy;
    hi  = m1 & cy;
}

// ---- fused 27-tap blur v3: LUT-free, PRMT magic-float, shfl halos ----
// thread = (y, word). g(z) = p00*C + p01*Ecnt + p11*Kcnt per cell (via SWAR
// bit transpose + byte->float magic), then 3-tap z blur in registers.
__global__ __launch_bounds__(256)
void blur_fused3_kernel(float4* __restrict__ out,
                        float a0, float a1,
                        float p00, float p01, float p11, float gmax) {
    __shared__ uint32_t sB[34][3][8];     // [y0-1..y0+32][x-1..x+1][word]
    __shared__ float4   sOut[2048];       // transpose buffer, swizzled

    int t  = threadIdx.x;
    int x  = blockIdx.x >> 3;
    int y0 = (blockIdx.x & 7) << 5;

    for (int c = t; c < 816; c += 256) {           // 8 words * 3 x * 34 y
        int w  = c / 102;
        int r  = c % 102;
        int xi = r / 34, yy = r % 34;
        int gx = (x + xi - 1) & 255;
        int gy = (y0 + yy - 1) & 255;
        sB[yy][xi][w] = g_solvb[(w << 16) | (gx << 8) | gy];
    }
    __syncthreads();

    int yl   = t >> 3;        // 0..31
    int w    = t & 7;         // word
    int lane = t & 31;

    uint32_t cc = sB[yl+1][1][w];
    uint32_t ea = sB[yl+1][0][w], eb = sB[yl+1][2][w];
    uint32_t ec = sB[yl  ][1][w], ed = sB[yl+2][1][w];
    uint32_t ka = sB[yl  ][0][w], kb = sB[yl  ][2][w];
    uint32_t kc = sB[yl+2][0][w], kd = sB[yl+2][2][w];
    uint32_t or9  = cc|ea|eb|ec|ed|ka|kb|kc|kd;
    uint32_t and9 = cc&ea&eb&ec&ed&ka&kb&kc&kd;

    float gz[34];             // gz[1..32] = own cells z=0..31; [0],[33] halos
    if (or9 == 0u) {
        #pragma unroll
        for (int z = 1; z <= 32; z++) gz[z] = 0.f;
    } else if (and9 == 0xffffffffu) {
        #pragma unroll
        for (int z = 1; z <= 32; z++) gz[z] = gmax;
    } else {
        uint32_t E0, E1, E2, K0, K1, K2;
        csa4(ea, eb, ec, ed, E0, E1, E2);
        csa4(ka, kb, kc, kd, K0, K1, K2);
        #pragma unroll
        for (int G = 0; G < 4; G++) {
            // pack byte G of planes [E0,E1,E2,C | K0,K1,K2,0] into 64 bits
            uint32_t sel = (uint32_t)G | ((uint32_t)(4 + G) << 4);
            uint32_t t01 = __byte_perm(E0, E1, sel);
            uint32_t t23 = __byte_perm(E2, cc, sel);
            uint32_t t45 = __byte_perm(K0, K1, sel);
            uint32_t t67 = __byte_perm(K2, 0u, sel);
            uint32_t lo  = __byte_perm(t01, t23, 0x5410);
            uint32_t hi  = __byte_perm(t45, t67, 0x5410);
            // 8x8 bit transpose: byte p, bit z  ->  byte z, bit p
            unsigned long long xb = (unsigned long long)lo
                                  | ((unsigned long long)hi << 32);
            unsigned long long yb;
            yb = (xb ^ (xb >> 7))  & 0x00AA00AA00AA00AAULL; xb ^= yb ^ (yb << 7);
            yb = (xb ^ (xb >> 14)) & 0x0000CCCC0000CCCCULL; xb ^= yb ^ (yb << 14);
            yb = (xb ^ (xb >> 28)) & 0x00000000F0F0F0F0ULL; xb ^= yb ^ (yb << 28);
            uint32_t blo = (uint32_t)xb, bhi = (uint32_t)(xb >> 32);
            #pragma unroll
            for (int half = 0; half < 2; half++) {
                uint32_t b  = half ? bhi : blo;
                uint32_t Ew = b & 0x07070707u;          // edge counts per byte
                uint32_t Cw = (b >> 3) & 0x01010101u;   // center bit per byte
                uint32_t Kw = (b >> 4) & 0x07070707u;   // corner counts per byte
                #pragma unroll
                for (int j = 0; j < 4; j++) {
                    uint32_t s2 = 0x7540u | (uint32_t)j;
                    float fE = __uint_as_float(__byte_perm(Ew, 0x4B000000u, s2)) - 8388608.f;
                    float fC = __uint_as_float(__byte_perm(Cw, 0x4B000000u, s2)) - 8388608.f;
                    float fK = __uint_as_float(__byte_perm(Kw, 0x4B000000u, s2)) - 8388608.f;
                    gz[1 + (G << 3) + (half << 2) + j] =
                        fmaf(p00, fC, fmaf(p01, fE, p11 * fK));
                }
            }
        }
    }

    // halos from neighbor words (adjacent lanes, z periodic within column)
    __syncwarp();
    int base = lane & 24;
    gz[0]  = __shfl_sync(0xffffffffu, gz[32], base | ((w + 7) & 7));
    gz[33] = __shfl_sync(0xffffffffu, gz[1],  base | ((w + 1) & 7));

    // 3-tap z blur + pack to float4, swizzled transpose store
    #pragma unroll
    for (int k = 0; k < 8; k++) {
        float4 o;
        o.x = fmaf(a0, gz[4*k+1], a1 * (gz[4*k+0] + gz[4*k+2]));
        o.y = fmaf(a0, gz[4*k+2], a1 * (gz[4*k+1] + gz[4*k+3]));
        o.z = fmaf(a0, gz[4*k+3], a1 * (gz[4*k+2] + gz[4*k+4]));
        o.w = fmaf(a0, gz[4*k+4], a1 * (gz[4*k+3] + gz[4*k+5]));
        sOut[(yl << 6) + (w << 3) + (k ^ w)] = o;
    }
    __syncthreads();

    #pragma unroll
    for (int k2 = 0; k2 < 8; k2++) {
        int flat = (k2 << 8) + t;
        int yy2 = flat >> 6;
        int zg2 = flat & 63;
        float4 v = sOut[(yy2 << 6) + (zg2 ^ (zg2 >> 3))];
        out[(x << 14) | ((y0 + yy2) << 6) | zg2] = v;
    }
}

extern "C" void kernel_launch(void* const* d_in, const int* in_sizes, int n_in,
                              void* d_out, int out_size) {
    const float* xyz = (const float*)d_in[0];
    const float* vdw = (const float*)d_in[1];
    int n_atoms = in_sizes[1];

    // all double math on the HOST; device sees only f32
    double sigma = 1.1 / (100.0 / 256.0) / 4.0;
    double w = exp(-1.0 / (2.0 * sigma * sigma));
    double s = 1.0 + 2.0 * w;
    double a0d = 1.0 / s, a1d = w / s;
    float a0  = (float)a0d;
    float a1  = (float)a1d;
    float p00 = (float)(a0d * a0d);
    float p01 = (float)(a0d * a1d);
    float p11 = (float)(a1d * a1d);
    float gmax = (float)(a0d * a0d + 4.0 * a0d * a1d + 4.0 * a1d * a1d);

    zero_kernel       <<<1024, 256>>>();
    splat_kernel      <<<(n_atoms + 3) / 4, 128>>>(xyz, vdw, n_atoms);
    classify_kernel   <<<256, 256>>>();
    blur_fused3_kernel<<<2048, 256>>>((float4*)d_out, a0, a1, p00, p01, p11, gmax);
}

// round 9
// speedup vs baseline: 3.1069x; 1.0060x over previous
#include <cuda_runtime.h>
#include <math.h>
#include <stdint.h>

#define NG   256
#define NG3  16777216
#define NW   (NG3/32)           // 524288 z-words per mask
#define SP   0.390625f          // 100/256, exact in f32

// combined grid: per z-word, lo32 = occ bits, hi32 = prot bits
// zero-initialized at module load; blur_fused4 re-zeroes it each call.
static __device__ unsigned long long g_bits[NW];
static __device__ uint32_t           g_solvb[NW];

// smallest float T with (s < T) <=> (sqrt_rn(s) < R)
__device__ __forceinline__ float cut_threshold(float R) {
    float t = __fmul_rn(R, R);
    while (__fsqrt_rn(t) >= R)
        t = __uint_as_float(__float_as_uint(t) - 1u);
    while (__fsqrt_rn(__uint_as_float(__float_as_uint(t) + 1u)) < R)
        t = __uint_as_float(__float_as_uint(t) + 1u);
    return __uint_as_float(__float_as_uint(t) + 1u);
}

// ---- splat: one warp per atom, branch-free 17-cell mask per (dx,dy) ----
__global__ void splat_kernel(const float* __restrict__ xyz,
                             const float* __restrict__ vdw,
                             int n_atoms) {
    int a = blockIdx.x * 4 + (threadIdx.x >> 5);
    if (a >= n_atoms) return;
    int lane = threadIdx.x & 31;
    float ax = xyz[3*a], ay = xyz[3*a+1], az = xyz[3*a+2];
    float vr = vdw[a];
    float R    = __fadd_rn(vr, 1.1f);
    float Tocc = cut_threshold(R);
    float Tpro = cut_threshold(vr);

    int bx = (int)floorf(__fdiv_rn(ax, SP));
    int by = (int)floorf(__fdiv_rn(ay, SP));
    int bz = (int)floorf(__fdiv_rn(az, SP));
    int zs = bz - 8;

    for (int p = lane; p < 289; p += 32) {
        int dx = p / 17 - 8;
        int dy = p % 17 - 8;
        int cx = bx + dx, cy = by + dy;
        float rx = __fsub_rn(__fmul_rn((float)cx, SP), ax);
        float ry = __fsub_rn(__fmul_rn((float)cy, SP), ay);
        float rxy2 = __fadd_rn(__fmul_rn(rx, rx), __fmul_rn(ry, ry));
        if (rxy2 >= Tocc) continue;           // exact: s >= rxy2

        unsigned mO = 0, mP = 0;
        #pragma unroll
        for (int j = 0; j < 17; ++j) {        // exact ref predicate per cell
            float rz = __fsub_rn(__fmul_rn((float)(zs + j), SP), az);
            float s  = __fadd_rn(rxy2, __fmul_rn(rz, rz));
            if (s < Tocc) mO |= 1u << j;
            if (s < Tpro) mP |= 1u << j;
        }
        if (!mO) continue;

        int s0 = zs & 255;
        int w0 = s0 >> 5, off = s0 & 31;
        unsigned long long osh = ((unsigned long long)mO) << off;
        unsigned long long psh = ((unsigned long long)mP) << off;
        int colbase = ((cx & 255) << 8) | (cy & 255);
        unsigned long long v0 = ((unsigned long long)(unsigned)psh << 32)
                              |  (unsigned long long)(unsigned)osh;
        unsigned long long v1 = ((unsigned long long)(unsigned)(psh >> 32) << 32)
                              |  (unsigned long long)(unsigned)(osh >> 32);
        if (v0) atomicOr(&g_bits[(w0 << 16) + colbase], v0);
        if (v1) atomicOr(&g_bits[((((w0 + 1) & 7)) << 16) + colbase], v1);
    }
}

// ---- classify: solv = ds | (nb & ~prot), bitwise erosion ----
__global__ void classify_kernel() {
    __shared__ uint32_t sD0[8 * 400];
    __shared__ uint32_t sD1[8 * 400];
    __shared__ uint32_t sD2[8 * 400];
    int bx0 = (blockIdx.x & 15) * 16;
    int by0 = (blockIdx.x >> 4) * 16;
    int t = threadIdx.x;

    for (int c = t; c < 400; c += 256) {
        int lx = c % 20, ly = c / 20;
        int gx = (bx0 + lx - 2) & 255;
        int gy = (by0 + ly - 2) & 255;
        int col = (gx << 8) | gy;
        uint32_t ds[8], d1[8], d2[8];
        #pragma unroll
        for (int i = 0; i < 8; i++)
            ds[i] = ~(uint32_t)g_bits[(i << 16) + col];
        #pragma unroll
        for (int i = 0; i < 8; i++)
            d1[i] = ds[i] | (ds[i] << 1) | (ds[(i+7)&7] >> 31)
                          | (ds[i] >> 1) | (ds[(i+1)&7] << 31);
        #pragma unroll
        for (int i = 0; i < 8; i++)
            d2[i] = d1[i] | (d1[i] << 1) | (d1[(i+7)&7] >> 31)
                          | (d1[i] >> 1) | (d1[(i+1)&7] << 31);
        #pragma unroll
        for (int i = 0; i < 8; i++) {
            sD0[i*400 + c] = ds[i];
            sD1[i*400 + c] = d1[i];
            sD2[i*400 + c] = d2[i];
        }
    }
    __syncthreads();

    int lx = (t & 15) + 2, ly = (t >> 4) + 2;
    int gx = (bx0 + lx - 2) & 255;
    int gy = (by0 + ly - 2) & 255;
    int col = (gx << 8) | gy;
    int cc = ly * 20 + lx;
    #pragma unroll
    for (int i = 0; i < 8; i++) {
        const uint32_t* D0 = sD0 + i * 400;
        const uint32_t* D1 = sD1 + i * 400;
        const uint32_t* D2 = sD2 + i * 400;
        uint32_t nb =
            D2[cc] | D2[cc+1]  | D2[cc-1]  | D2[cc+20] | D2[cc-20] |
            D1[cc+21] | D1[cc+19] | D1[cc-19] | D1[cc-21] |
            D1[cc+2]  | D1[cc-2]  | D1[cc+40] | D1[cc-40] |
            D0[cc+22] | D0[cc+18] | D0[cc-18] | D0[cc-22] |
            D0[cc+41] | D0[cc+39] | D0[cc-39] | D0[cc-41];
        uint32_t p = (uint32_t)(g_bits[(i << 16) + col] >> 32);
        g_solvb[(i << 16) + col] = D0[cc] | (nb & ~p);
    }
}

// CSA of 4 one-bit vectors: sum = lo + 2*mid + 4*hi
__device__ __forceinline__ void csa4(uint32_t a, uint32_t b, uint32_t c, uint32_t d,
                                     uint32_t& lo, uint32_t& mid, uint32_t& hi) {
    uint32_t s1 = a ^ b ^ c;
    uint32_t m1 = (a & b) | (c & (a | b));
    uint32_t cy = s1 & d;
    lo  = s1 ^ d;
    mid = m1 ^ cy;
    hi  = m1 & cy;
}

// ---- fused 27-tap blur v4: z-coherent warps (lane=y, warp=word) ----
// Whole warps in uniform regions skip the transpose/convert block.
// Also re-zeroes g_bits for the next call (replaces zero_kernel).
__global__ __launch_bounds__(256)
void blur_fused4_kernel(float4* __restrict__ out,
                        float a0, float a1,
                        float p00, float p01, float p11, float gmax) {
    __shared__ uint32_t sB[8][3][34];     // [word][x-1..x+1][y0-1..y0+32]
    __shared__ float    sHi[8][32];       // gz[32] per (word, y)
    __shared__ float    sLo[8][32];       // gz[1]  per (word, y)
    __shared__ float4   sOut[2048];       // transpose buffer, swizzled

    int t  = threadIdx.x;
    int x  = blockIdx.x >> 3;
    int y0 = (blockIdx.x & 7) << 5;

    // re-zero splat grid for the next kernel_launch call
    g_bits[blockIdx.x * 256 + t] = 0ULL;

    for (int c = t; c < 816; c += 256) {           // 8 words * 3 x * 34 y
        int w  = c / 102;
        int r  = c % 102;
        int xi = r / 34, yy = r % 34;
        int gx = (x + xi - 1) & 255;
        int gy = (y0 + yy - 1) & 255;
        sB[w][xi][yy] = g_solvb[(w << 16) | (gx << 8) | gy];
    }
    __syncthreads();

    int yl = t & 31;          // lane = y
    int w  = t >> 5;          // warp = word

    uint32_t cc = sB[w][1][yl+1];
    uint32_t ea = sB[w][0][yl+1], eb = sB[w][2][yl+1];
    uint32_t ec = sB[w][1][yl  ], ed = sB[w][1][yl+2];
    uint32_t ka = sB[w][0][yl  ], kb = sB[w][0][yl+2];
    uint32_t kc = sB[w][2][yl  ], kd = sB[w][2][yl+2];
    uint32_t or9  = cc|ea|eb|ec|ed|ka|kb|kc|kd;
    uint32_t and9 = cc&ea&eb&ec&ed&ka&kb&kc&kd;

    float gz[34];             // gz[1..32] = own cells z=0..31; [0],[33] halos
    if (__all_sync(0xffffffffu, or9 == 0u)) {
        #pragma unroll
        for (int z = 1; z <= 32; z++) gz[z] = 0.f;
    } else if (__all_sync(0xffffffffu, and9 == 0xffffffffu)) {
        #pragma unroll
        for (int z = 1; z <= 32; z++) gz[z] = gmax;
    } else {
        uint32_t E0, E1, E2, K0, K1, K2;
        csa4(ea, eb, ec, ed, E0, E1, E2);
        csa4(ka, kb, kc, kd, K0, K1, K2);
        #pragma unroll
        for (int G = 0; G < 4; G++) {
            // pack byte G of planes [E0,E1,E2,C | K0,K1,K2,0] into 64 bits
            uint32_t sel = (uint32_t)G | ((uint32_t)(4 + G) << 4);
            uint32_t t01 = __byte_perm(E0, E1, sel);
            uint32_t t23 = __byte_perm(E2, cc, sel);
            uint32_t t45 = __byte_perm(K0, K1, sel);
            uint32_t t67 = __byte_perm(K2, 0u, sel);
            uint32_t lo  = __byte_perm(t01, t23, 0x5410);
            uint32_t hi  = __byte_perm(t45, t67, 0x5410);
            // 8x8 bit transpose: byte p, bit z  ->  byte z, bit p
            unsigned long long xb = (unsigned long long)lo
                                  | ((unsigned long long)hi << 32);
            unsigned long long yb;
            yb = (xb ^ (xb >> 7))  & 0x00AA00AA00AA00AAULL; xb ^= yb ^ (yb << 7);
            yb = (xb ^ (xb >> 14)) & 0x0000CCCC0000CCCCULL; xb ^= yb ^ (yb << 14);
            yb = (xb ^ (xb >> 28)) & 0x00000000F0F0F0F0ULL; xb ^= yb ^ (yb << 28);
            uint32_t blo = (uint32_t)xb, bhi = (uint32_t)(xb >> 32);
            #pragma unroll
            for (int half = 0; half < 2; half++) {
                uint32_t b  = half ? bhi : blo;
                uint32_t Ew = b & 0x07070707u;          // edge counts per byte
                uint32_t Cw = (b >> 3) & 0x01010101u;   // center bit per byte
                uint32_t Kw = (b >> 4) & 0x07070707u;   // corner counts per byte
                #pragma unroll
                for (int j = 0; j < 4; j++) {
                    uint32_t s2 = 0x7540u | (uint32_t)j;
                    float fE = __uint_as_float(__byte_perm(Ew, 0x4B000000u, s2)) - 8388608.f;
                    float fC = __uint_as_float(__byte_perm(Cw, 0x4B000000u, s2)) - 8388608.f;
                    float fK = __uint_as_float(__byte_perm(Kw, 0x4B000000u, s2)) - 8388608.f;
                    gz[1 + (G << 3) + (half << 2) + j] =
                        fmaf(p00, fC, fmaf(p01, fE, p11 * fK));
                }
            }
        }
    }

    // word halos via smem (neighbor word lives in another warp now)
    sLo[w][yl] = gz[1];
    sHi[w][yl] = gz[32];
    __syncthreads();
    gz[0]  = sHi[(w + 7) & 7][yl];
    gz[33] = sLo[(w + 1) & 7][yl];

    // 3-tap z blur + pack to float4, y-swizzled transpose store
    #pragma unroll
    for (int k = 0; k < 8; k++) {
        float4 o;
        o.x = fmaf(a0, gz[4*k+1], a1 * (gz[4*k+0] + gz[4*k+2]));
        o.y = fmaf(a0, gz[4*k+2], a1 * (gz[4*k+1] + gz[4*k+3]));
        o.z = fmaf(a0, gz[4*k+3], a1 * (gz[4*k+2] + gz[4*k+4]));
        o.w = fmaf(a0, gz[4*k+4], a1 * (gz[4*k+3] + gz[4*k+5]));
        sOut[(yl << 6) + (((w << 3) + k) ^ yl)] = o;
    }
    __syncthreads();

    #pragma unroll
    for (int k2 = 0; k2 < 8; k2++) {
        int flat = (k2 << 8) + t;
        int yy2 = flat >> 6;          // 0..31
        int zg2 = flat & 63;
        float4 v = sOut[(yy2 << 6) + (zg2 ^ yy2)];
        out[(x << 14) | ((y0 + yy2) << 6) | zg2] = v;
    }
}

extern "C" void kernel_launch(void* const* d_in, const int* in_sizes, int n_in,
                              void* d_out, int out_size) {
    const float* xyz = (const float*)d_in[0];
    const float* vdw = (const float*)d_in[1];
    int n_atoms = in_sizes[1];

    // all double math on the HOST; device sees only f32
    double sigma = 1.1 / (100.0 / 256.0) / 4.0;
    double w = exp(-1.0 / (2.0 * sigma * sigma));
    double s = 1.0 + 2.0 * w;
    double a0d = 1.0 / s, a1d = w / s;
    float a0  = (float)a0d;
    float a1  = (float)a1d;
    float p00 = (float)(a0d * a0d);
    float p01 = (float)(a0d * a1d);
    float p11 = (float)(a1d * a1d);
    float gmax = (float)(a0d * a0d + 4.0 * a0d * a1d + 4.0 * a1d * a1d);

    splat_kernel      <<<(n_atoms + 3) / 4, 128>>>(xyz, vdw, n_atoms);
    classify_kernel   <<<256, 256>>>();
    blur_fused4_kernel<<<2048, 256>>>((float4*)d_out, a0, a1, p00, p01, p11, gmax);
}

// round 10
// speedup vs baseline: 3.3993x; 1.0941x over previous
#include <cuda_runtime.h>
#include <math.h>
#include <stdint.h>

#define NG   256
#define NG3  16777216
#define NW   (NG3/32)           // 524288 z-words per mask
#define SP   0.390625f          // 100/256, exact in f32

// combined grid: per z-word, lo32 = occ bits, hi32 = prot bits
// zero-initialized at module load; blur_fused4 re-zeroes it each call.
static __device__ unsigned long long g_bits[NW];
static __device__ uint32_t           g_solvb[NW];

// smallest float T with (s < T) <=> (sqrt_rn(s) < R)
__device__ __forceinline__ float cut_threshold(float R) {
    float t = __fmul_rn(R, R);
    while (__fsqrt_rn(t) >= R)
        t = __uint_as_float(__float_as_uint(t) - 1u);
    while (__fsqrt_rn(__uint_as_float(__float_as_uint(t) + 1u)) < R)
        t = __uint_as_float(__float_as_uint(t) + 1u);
    return __uint_as_float(__float_as_uint(t) + 1u);
}

// exact reference predicate: fadd(rxy2, fmul(rz,rz)) < T, rz single-rounded
__device__ __forceinline__ bool cell_pass(int zc, float az, float rxy2, float T) {
    float rz = __fmaf_rn((float)zc, SP, -az);   // == fsub(fmul_exact, az)
    float s  = __fadd_rn(rxy2, __fmul_rn(rz, rz));
    return s < T;
}

// contiguous passing z-interval [lo,hi] for threshold T (given rxy2 < T).
// Estimate via sqrt with guarded error bound, resolve each boundary with ONE
// exact predicate eval (estimate is provably in {first_inside-1, first_inside}).
__device__ __forceinline__ void chord_bounds(float az, float rxy2, float T,
                                             int& lo, int& hi) {
    float t = __fsub_rn(T, rxy2);               // >= 0
    float h = __fsqrt_rn(t);
    int zl0 = (int)ceilf (__fmaf_rn(az - h, 2.56f, -1.25e-4f));
    int zh0 = (int)floorf(__fmaf_rn(az + h, 2.56f,  1.25e-4f));
    lo = cell_pass(zl0, az, rxy2, T) ? zl0 : zl0 + 1;
    hi = cell_pass(zh0, az, rxy2, T) ? zh0 : zh0 - 1;
}

// ---- splat: one warp per atom, analytic chord masks per (dx,dy) ----
__global__ void splat_kernel(const float* __restrict__ xyz,
                             const float* __restrict__ vdw,
                             int n_atoms) {
    int a = blockIdx.x * 4 + (threadIdx.x >> 5);
    if (a >= n_atoms) return;
    int lane = threadIdx.x & 31;
    float ax = xyz[3*a], ay = xyz[3*a+1], az = xyz[3*a+2];
    float vr = vdw[a];
    float R    = __fadd_rn(vr, 1.1f);
    float Tocc = cut_threshold(R);
    float Tpro = cut_threshold(vr);

    int bx = (int)floorf(__fdiv_rn(ax, SP));
    int by = (int)floorf(__fdiv_rn(ay, SP));
    int bz = (int)floorf(__fdiv_rn(az, SP));
    int zs = bz - 8;

    for (int p = lane; p < 289; p += 32) {
        int dx = p / 17 - 8;
        int dy = p % 17 - 8;
        int cx = bx + dx, cy = by + dy;
        float rx = __fsub_rn(__fmul_rn((float)cx, SP), ax);
        float ry = __fsub_rn(__fmul_rn((float)cy, SP), ay);
        float rxy2 = __fadd_rn(__fmul_rn(rx, rx), __fmul_rn(ry, ry));
        if (rxy2 >= Tocc) continue;           // exact cull (s >= rxy2)

        int lo, hi;
        chord_bounds(az, rxy2, Tocc, lo, hi);
        lo = max(lo, bz - 8);
        hi = min(hi, bz + 8);                 // reference window truncation
        if (hi < lo) continue;
        unsigned mO = (2u << (hi - zs)) - (1u << (lo - zs));

        unsigned mP = 0;
        if (rxy2 < Tpro) {
            int pl, ph;
            chord_bounds(az, rxy2, Tpro, pl, ph);
            pl = max(pl, bz - 8);
            ph = min(ph, bz + 8);
            if (ph >= pl) mP = (2u << (ph - zs)) - (1u << (pl - zs));
        }

        int s0 = zs & 255;
        int w0 = s0 >> 5, off = s0 & 31;
        unsigned long long osh = ((unsigned long long)mO) << off;
        unsigned long long psh = ((unsigned long long)mP) << off;
        int colbase = ((cx & 255) << 8) | (cy & 255);
        unsigned long long v0 = ((unsigned long long)(unsigned)psh << 32)
                              |  (unsigned long long)(unsigned)osh;
        unsigned long long v1 = ((unsigned long long)(unsigned)(psh >> 32) << 32)
                              |  (unsigned long long)(unsigned)(osh >> 32);
        if (v0) atomicOr(&g_bits[(w0 << 16) + colbase], v0);
        if (v1) atomicOr(&g_bits[((((w0 + 1) & 7)) << 16) + colbase], v1);
    }
}

// ---- classify: solv = ds | (nb & ~prot), bitwise erosion ----
__global__ void classify_kernel() {
    __shared__ uint32_t sD0[8 * 400];
    __shared__ uint32_t sD1[8 * 400];
    __shared__ uint32_t sD2[8 * 400];
    int bx0 = (blockIdx.x & 15) * 16;
    int by0 = (blockIdx.x >> 4) * 16;
    int t = threadIdx.x;

    for (int c = t; c < 400; c += 256) {
        int lx = c % 20, ly = c / 20;
        int gx = (bx0 + lx - 2) & 255;
        int gy = (by0 + ly - 2) & 255;
        int col = (gx << 8) | gy;
        uint32_t ds[8], d1[8], d2[8];
        #pragma unroll
        for (int i = 0; i < 8; i++)
            ds[i] = ~(uint32_t)g_bits[(i << 16) + col];
        #pragma unroll
        for (int i = 0; i < 8; i++)
            d1[i] = ds[i] | (ds[i] << 1) | (ds[(i+7)&7] >> 31)
                          | (ds[i] >> 1) | (ds[(i+1)&7] << 31);
        #pragma unroll
        for (int i = 0; i < 8; i++)
            d2[i] = d1[i] | (d1[i] << 1) | (d1[(i+7)&7] >> 31)
                          | (d1[i] >> 1) | (d1[(i+1)&7] << 31);
        #pragma unroll
        for (int i = 0; i < 8; i++) {
            sD0[i*400 + c] = ds[i];
            sD1[i*400 + c] = d1[i];
            sD2[i*400 + c] = d2[i];
        }
    }
    __syncthreads();

    int lx = (t & 15) + 2, ly = (t >> 4) + 2;
    int gx = (bx0 + lx - 2) & 255;
    int gy = (by0 + ly - 2) & 255;
    int col = (gx << 8) | gy;
    int cc = ly * 20 + lx;
    #pragma unroll
    for (int i = 0; i < 8; i++) {
        const uint32_t* D0 = sD0 + i * 400;
        const uint32_t* D1 = sD1 + i * 400;
        const uint32_t* D2 = sD2 + i * 400;
        uint32_t nb =
            D2[cc] | D2[cc+1]  | D2[cc-1]  | D2[cc+20] | D2[cc-20] |
            D1[cc+21] | D1[cc+19] | D1[cc-19] | D1[cc-21] |
            D1[cc+2]  | D1[cc-2]  | D1[cc+40] | D1[cc-40] |
            D0[cc+22] | D0[cc+18] | D0[cc-18] | D0[cc-22] |
            D0[cc+41] | D0[cc+39] | D0[cc-39] | D0[cc-41];
        uint32_t p = (uint32_t)(g_bits[(i << 16) + col] >> 32);
        g_solvb[(i << 16) + col] = D0[cc] | (nb & ~p);
    }
}

// CSA of 4 one-bit vectors: sum = lo + 2*mid + 4*hi
__device__ __forceinline__ void csa4(uint32_t a, uint32_t b, uint32_t c, uint32_t d,
                                     uint32_t& lo, uint32_t& mid, uint32_t& hi) {
    uint32_t s1 = a ^ b ^ c;
    uint32_t m1 = (a & b) | (c & (a | b));
    uint32_t cy = s1 & d;
    lo  = s1 ^ d;
    mid = m1 ^ cy;
    hi  = m1 & cy;
}

// ---- fused 27-tap blur v4: z-coherent warps (lane=y, warp=word) ----
// Whole warps in uniform regions skip the transpose/convert block.
// Also re-zeroes g_bits for the next call (replaces zero_kernel).
__global__ __launch_bounds__(256)
void blur_fused4_kernel(float4* __restrict__ out,
                        float a0, float a1,
                        float p00, float p01, float p11, float gmax) {
    __shared__ uint32_t sB[8][3][34];     // [word][x-1..x+1][y0-1..y0+32]
    __shared__ float    sHi[8][32];       // gz[32] per (word, y)
    __shared__ float    sLo[8][32];       // gz[1]  per (word, y)
    __shared__ float4   sOut[2048];       // transpose buffer, swizzled

    int t  = threadIdx.x;
    int x  = blockIdx.x >> 3;
    int y0 = (blockIdx.x & 7) << 5;

    // re-zero splat grid for the next kernel_launch call
    g_bits[blockIdx.x * 256 + t] = 0ULL;

    for (int c = t; c < 816; c += 256) {           // 8 words * 3 x * 34 y
        int w  = c / 102;
        int r  = c % 102;
        int xi = r / 34, yy = r % 34;
        int gx = (x + xi - 1) & 255;
        int gy = (y0 + yy - 1) & 255;
        sB[w][xi][yy] = g_solvb[(w << 16) | (gx << 8) | gy];
    }
    __syncthreads();

    int yl = t & 31;          // lane = y
    int w  = t >> 5;          // warp = word

    uint32_t cc = sB[w][1][yl+1];
    uint32_t ea = sB[w][0][yl+1], eb = sB[w][2][yl+1];
    uint32_t ec = sB[w][1][yl  ], ed = sB[w][1][yl+2];
    uint32_t ka = sB[w][0][yl  ], kb = sB[w][0][yl+2];
    uint32_t kc = sB[w][2][yl  ], kd = sB[w][2][yl+2];
    uint32_t or9  = cc|ea|eb|ec|ed|ka|kb|kc|kd;
    uint32_t and9 = cc&ea&eb&ec&ed&ka&kb&kc&kd;

    float gz[34];             // gz[1..32] = own cells z=0..31; [0],[33] halos
    if (__all_sync(0xffffffffu, or9 == 0u)) {
        #pragma unroll
        for (int z = 1; z <= 32; z++) gz[z] = 0.f;
    } else if (__all_sync(0xffffffffu, and9 == 0xffffffffu)) {
        #pragma unroll
        for (int z = 1; z <= 32; z++) gz[z] = gmax;
    } else {
        uint32_t E0, E1, E2, K0, K1, K2;
        csa4(ea, eb, ec, ed, E0, E1, E2);
        csa4(ka, kb, kc, kd, K0, K1, K2);
        #pragma unroll
        for (int G = 0; G < 4; G++) {
            // pack byte G of planes [E0,E1,E2,C | K0,K1,K2,0] into 64 bits
            uint32_t sel = (uint32_t)G | ((uint32_t)(4 + G) << 4);
            uint32_t t01 = __byte_perm(E0, E1, sel);
            uint32_t t23 = __byte_perm(E2, cc, sel);
            uint32_t t45 = __byte_perm(K0, K1, sel);
            uint32_t t67 = __byte_perm(K2, 0u, sel);
            uint32_t lo  = __byte_perm(t01, t23, 0x5410);
            uint32_t hi  = __byte_perm(t45, t67, 0x5410);
            // 8x8 bit transpose: byte p, bit z  ->  byte z, bit p
            unsigned long long xb = (unsigned long long)lo
                                  | ((unsigned long long)hi << 32);
            unsigned long long yb;
            yb = (xb ^ (xb >> 7))  & 0x00AA00AA00AA00AAULL; xb ^= yb ^ (yb << 7);
            yb = (xb ^ (xb >> 14)) & 0x0000CCCC0000CCCCULL; xb ^= yb ^ (yb << 14);
            yb = (xb ^ (xb >> 28)) & 0x00000000F0F0F0F0ULL; xb ^= yb ^ (yb << 28);
            uint32_t blo = (uint32_t)xb, bhi = (uint32_t)(xb >> 32);
            #pragma unroll
            for (int half = 0; half < 2; half++) {
                uint32_t b  = half ? bhi : blo;
                uint32_t Ew = b & 0x07070707u;          // edge counts per byte
                uint32_t Cw = (b >> 3) & 0x01010101u;   // center bit per byte
                uint32_t Kw = (b >> 4) & 0x07070707u;   // corner counts per byte
                #pragma unroll
                for (int j = 0; j < 4; j++) {
                    uint32_t s2 = 0x7540u | (uint32_t)j;
                    float fE = __uint_as_float(__byte_perm(Ew, 0x4B000000u, s2)) - 8388608.f;
                    float fC = __uint_as_float(__byte_perm(Cw, 0x4B000000u, s2)) - 8388608.f;
                    float fK = __uint_as_float(__byte_perm(Kw, 0x4B000000u, s2)) - 8388608.f;
                    gz[1 + (G << 3) + (half << 2) + j] =
                        fmaf(p00, fC, fmaf(p01, fE, p11 * fK));
                }
            }
        }
    }

    // word halos via smem (neighbor word lives in another warp now)
    sLo[w][yl] = gz[1];
    sHi[w][yl] = gz[32];
    __syncthreads();
    gz[0]  = sHi[(w + 7) & 7][yl];
    gz[33] = sLo[(w + 1) & 7][yl];

    // 3-tap z blur + pack to float4, y-swizzled transpose store
    #pragma unroll
    for (int k = 0; k < 8; k++) {
        float4 o;
        o.x = fmaf(a0, gz[4*k+1], a1 * (gz[4*k+0] + gz[4*k+2]));
        o.y = fmaf(a0, gz[4*k+2], a1 * (gz[4*k+1] + gz[4*k+3]));
        o.z = fmaf(a0, gz[4*k+3], a1 * (gz[4*k+2] + gz[4*k+4]));
        o.w = fmaf(a0, gz[4*k+4], a1 * (gz[4*k+3] + gz[4*k+5]));
        sOut[(yl << 6) + (((w << 3) + k) ^ yl)] = o;
    }
    __syncthreads();

    #pragma unroll
    for (int k2 = 0; k2 < 8; k2++) {
        int flat = (k2 << 8) + t;
        int yy2 = flat >> 6;          // 0..31
        int zg2 = flat & 63;
        float4 v = sOut[(yy2 << 6) + (zg2 ^ yy2)];
        out[(x << 14) | ((y0 + yy2) << 6) | zg2] = v;
    }
}

extern "C" void kernel_launch(void* const* d_in, const int* in_sizes, int n_in,
                              void* d_out, int out_size) {
    const float* xyz = (const float*)d_in[0];
    const float* vdw = (const float*)d_in[1];
    int n_atoms = in_sizes[1];

    // all double math on the HOST; device sees only f32
    double sigma = 1.1 / (100.0 / 256.0) / 4.0;
    double w = exp(-1.0 / (2.0 * sigma * sigma));
    double s = 1.0 + 2.0 * w;
    double a0d = 1.0 / s, a1d = w / s;
    float a0  = (float)a0d;
    float a1  = (float)a1d;
    float p00 = (float)(a0d * a0d);
    float p01 = (float)(a0d * a1d);
    float p11 = (float)(a1d * a1d);
    float gmax = (float)(a0d * a0d + 4.0 * a0d * a1d + 4.0 * a1d * a1d);

    splat_kernel      <<<(n_atoms + 3) / 4, 128>>>(xyz, vdw, n_atoms);
    classify_kernel   <<<256, 256>>>();
    blur_fused4_kernel<<<2048, 256>>>((float4*)d_out, a0, a1, p00, p01, p11, gmax);
}

// round 11
// speedup vs baseline: 3.5671x; 1.0494x over previous
#include <cuda_runtime.h>
#include <math.h>
#include <stdint.h>

#define NG   256
#define NG3  16777216
#define NW   (NG3/32)           // 524288 z-words per mask
#define SP   0.390625f          // 100/256, exact in f32

// combined grid: per z-word, lo32 = occ bits, hi32 = prot bits
// zero-initialized at module load; blur_fused4 re-zeroes it each call.
static __device__ unsigned long long g_bits[NW];
static __device__ uint32_t           g_solvb[NW];

// smallest float T with (s < T) <=> (sqrt_rn(s) < R)
__device__ __forceinline__ float cut_threshold(float R) {
    float t = __fmul_rn(R, R);
    while (__fsqrt_rn(t) >= R)
        t = __uint_as_float(__float_as_uint(t) - 1u);
    while (__fsqrt_rn(__uint_as_float(__float_as_uint(t) + 1u)) < R)
        t = __uint_as_float(__float_as_uint(t) + 1u);
    return __uint_as_float(__float_as_uint(t) + 1u);
}

// exact reference predicate: fadd(rxy2, fmul(rz,rz)) < T, rz single-rounded
__device__ __forceinline__ bool cell_pass(int zc, float az, float rxy2, float T) {
    float rz = __fmaf_rn((float)zc, SP, -az);
    float s  = __fadd_rn(rxy2, __fmul_rn(rz, rz));
    return s < T;
}

// contiguous passing z-interval [lo,hi] for threshold T (given rxy2 < T)
__device__ __forceinline__ void chord_bounds(float az, float rxy2, float T,
                                             int& lo, int& hi) {
    float t = __fsub_rn(T, rxy2);               // >= 0
    float h = __fsqrt_rn(t);
    int zl0 = (int)ceilf (__fmaf_rn(az - h, 2.56f, -1.25e-4f));
    int zh0 = (int)floorf(__fmaf_rn(az + h, 2.56f,  1.25e-4f));
    lo = cell_pass(zl0, az, rxy2, T) ? zl0 : zl0 + 1;
    hi = cell_pass(zh0, az, rxy2, T) ? zh0 : zh0 - 1;
}

// ---- splat: TWO warps per atom (64 lanes over 289 cells) ----
__global__ void splat_kernel(const float* __restrict__ xyz,
                             const float* __restrict__ vdw,
                             int n_atoms) {
    int a = blockIdx.x * 4 + (threadIdx.x >> 6);
    if (a >= n_atoms) return;
    int lane = threadIdx.x & 63;
    float ax = xyz[3*a], ay = xyz[3*a+1], az = xyz[3*a+2];
    float vr = vdw[a];
    float R    = __fadd_rn(vr, 1.1f);
    float Tocc = cut_threshold(R);
    float Tpro = cut_threshold(vr);

    int bx = (int)floorf(__fdiv_rn(ax, SP));
    int by = (int)floorf(__fdiv_rn(ay, SP));
    int bz = (int)floorf(__fdiv_rn(az, SP));
    int zs = bz - 8;

    for (int p = lane; p < 289; p += 64) {
        int dx = p / 17 - 8;
        int dy = p % 17 - 8;
        int cx = bx + dx, cy = by + dy;
        float rx = __fsub_rn(__fmul_rn((float)cx, SP), ax);
        float ry = __fsub_rn(__fmul_rn((float)cy, SP), ay);
        float rxy2 = __fadd_rn(__fmul_rn(rx, rx), __fmul_rn(ry, ry));
        if (rxy2 >= Tocc) continue;           // exact cull (s >= rxy2)

        int lo, hi;
        chord_bounds(az, rxy2, Tocc, lo, hi);
        lo = max(lo, bz - 8);
        hi = min(hi, bz + 8);                 // reference window truncation
        if (hi < lo) continue;
        unsigned mO = (2u << (hi - zs)) - (1u << (lo - zs));

        unsigned mP = 0;
        if (rxy2 < Tpro) {
            int pl, ph;
            chord_bounds(az, rxy2, Tpro, pl, ph);
            pl = max(pl, bz - 8);
            ph = min(ph, bz + 8);
            if (ph >= pl) mP = (2u << (ph - zs)) - (1u << (pl - zs));
        }

        int s0 = zs & 255;
        int w0 = s0 >> 5, off = s0 & 31;
        unsigned long long osh = ((unsigned long long)mO) << off;
        unsigned long long psh = ((unsigned long long)mP) << off;
        int colbase = ((cx & 255) << 8) | (cy & 255);
        unsigned long long v0 = ((unsigned long long)(unsigned)psh << 32)
                              |  (unsigned long long)(unsigned)osh;
        unsigned long long v1 = ((unsigned long long)(unsigned)(psh >> 32) << 32)
                              |  (unsigned long long)(unsigned)(osh >> 32);
        if (v0) atomicOr(&g_bits[(w0 << 16) + colbase], v0);
        if (v1) atomicOr(&g_bits[((((w0 + 1) & 7)) << 16) + colbase], v1);
    }
}

// ---- classify: solv = ds | (nb & ~prot); coalesced (fast index -> gy) ----
__global__ void classify_kernel() {
    __shared__ uint32_t sD0[8 * 400];
    __shared__ uint32_t sD1[8 * 400];
    __shared__ uint32_t sD2[8 * 400];
    int bx0 = (blockIdx.x & 15) * 16;
    int by0 = (blockIdx.x >> 4) * 16;
    int t = threadIdx.x;

    for (int c = t; c < 400; c += 256) {
        int iy = c % 20, ix = c / 20;              // iy fast -> gy contiguous
        int gx = (bx0 + ix - 2) & 255;
        int gy = (by0 + iy - 2) & 255;
        int col = (gx << 8) | gy;
        uint32_t ds[8], d1[8], d2[8];
        #pragma unroll
        for (int i = 0; i < 8; i++)
            ds[i] = ~(uint32_t)g_bits[(i << 16) + col];
        #pragma unroll
        for (int i = 0; i < 8; i++)
            d1[i] = ds[i] | (ds[i] << 1) | (ds[(i+7)&7] >> 31)
                          | (ds[i] >> 1) | (ds[(i+1)&7] << 31);
        #pragma unroll
        for (int i = 0; i < 8; i++)
            d2[i] = d1[i] | (d1[i] << 1) | (d1[(i+7)&7] >> 31)
                          | (d1[i] >> 1) | (d1[(i+1)&7] << 31);
        #pragma unroll
        for (int i = 0; i < 8; i++) {
            sD0[i*400 + c] = ds[i];
            sD1[i*400 + c] = d1[i];
            sD2[i*400 + c] = d2[i];
        }
    }
    __syncthreads();

    int iy = (t & 15) + 2, ix = (t >> 4) + 2;      // iy fast -> gy contiguous
    int gx = (bx0 + ix - 2) & 255;
    int gy = (by0 + iy - 2) & 255;
    int col = (gx << 8) | gy;
    int cc = ix * 20 + iy;
    // offset pattern is xy-symmetric: cc+-1 = y+-1, cc+-20 = x+-1
    #pragma unroll
    for (int i = 0; i < 8; i++) {
        const uint32_t* D0 = sD0 + i * 400;
        const uint32_t* D1 = sD1 + i * 400;
        const uint32_t* D2 = sD2 + i * 400;
        uint32_t nb =
            D2[cc] | D2[cc+1]  | D2[cc-1]  | D2[cc+20] | D2[cc-20] |
            D1[cc+21] | D1[cc+19] | D1[cc-19] | D1[cc-21] |
            D1[cc+2]  | D1[cc-2]  | D1[cc+40] | D1[cc-40] |
            D0[cc+22] | D0[cc+18] | D0[cc-18] | D0[cc-22] |
            D0[cc+41] | D0[cc+39] | D0[cc-39] | D0[cc-41];
        uint32_t p = (uint32_t)(g_bits[(i << 16) + col] >> 32);
        g_solvb[(i << 16) + col] = D0[cc] | (nb & ~p);
    }
}

// CSA of 4 one-bit vectors: sum = lo + 2*mid + 4*hi
__device__ __forceinline__ void csa4(uint32_t a, uint32_t b, uint32_t c, uint32_t d,
                                     uint32_t& lo, uint32_t& mid, uint32_t& hi) {
    uint32_t s1 = a ^ b ^ c;
    uint32_t m1 = (a & b) | (c & (a | b));
    uint32_t cy = s1 & d;
    lo  = s1 ^ d;
    mid = m1 ^ cy;
    hi  = m1 & cy;
}

// ---- fused 27-tap blur v5: unconditional path (fog input => no fast path) ----
// Also re-zeroes g_bits for the next call.
__global__ __launch_bounds__(256)
void blur_fused5_kernel(float4* __restrict__ out,
                        float a0, float a1,
                        float p00, float p01, float p11) {
    __shared__ uint32_t sB[8][3][34];     // [word][x-1..x+1][y0-1..y0+32]
    __shared__ float    sHi[8][32];
    __shared__ float    sLo[8][32];
    __shared__ float4   sOut[2048];

    int t  = threadIdx.x;
    int x  = blockIdx.x >> 3;
    int y0 = (blockIdx.x & 7) << 5;

    // re-zero splat grid for the next kernel_launch call
    g_bits[blockIdx.x * 256 + t] = 0ULL;

    for (int c = t; c < 816; c += 256) {
        int w  = c / 102;
        int r  = c % 102;
        int xi = r / 34, yy = r % 34;
        int gx = (x + xi - 1) & 255;
        int gy = (y0 + yy - 1) & 255;
        sB[w][xi][yy] = g_solvb[(w << 16) | (gx << 8) | gy];
    }
    __syncthreads();

    int yl = t & 31;          // lane = y
    int w  = t >> 5;          // warp = word

    uint32_t cc = sB[w][1][yl+1];
    uint32_t ea = sB[w][0][yl+1], eb = sB[w][2][yl+1];
    uint32_t ec = sB[w][1][yl  ], ed = sB[w][1][yl+2];
    uint32_t ka = sB[w][0][yl  ], kb = sB[w][0][yl+2];
    uint32_t kc = sB[w][2][yl  ], kd = sB[w][2][yl+2];

    float gz[34];
    uint32_t E0, E1, E2, K0, K1, K2;
    csa4(ea, eb, ec, ed, E0, E1, E2);
    csa4(ka, kb, kc, kd, K0, K1, K2);
    #pragma unroll
    for (int G = 0; G < 4; G++) {
        uint32_t sel = (uint32_t)G | ((uint32_t)(4 + G) << 4);
        uint32_t t01 = __byte_perm(E0, E1, sel);
        uint32_t t23 = __byte_perm(E2, cc, sel);
        uint32_t t45 = __byte_perm(K0, K1, sel);
        uint32_t t67 = __byte_perm(K2, 0u, sel);
        uint32_t lo  = __byte_perm(t01, t23, 0x5410);
        uint32_t hi  = __byte_perm(t45, t67, 0x5410);
        unsigned long long xb = (unsigned long long)lo
                              | ((unsigned long long)hi << 32);
        unsigned long long yb;
        yb = (xb ^ (xb >> 7))  & 0x00AA00AA00AA00AAULL; xb ^= yb ^ (yb << 7);
        yb = (xb ^ (xb >> 14)) & 0x0000CCCC0000CCCCULL; xb ^= yb ^ (yb << 14);
        yb = (xb ^ (xb >> 28)) & 0x00000000F0F0F0F0ULL; xb ^= yb ^ (yb << 28);
        uint32_t blo = (uint32_t)xb, bhi = (uint32_t)(xb >> 32);
        #pragma unroll
        for (int half = 0; half < 2; half++) {
            uint32_t b  = half ? bhi : blo;
            uint32_t Ew = b & 0x07070707u;
            uint32_t Cw = (b >> 3) & 0x01010101u;
            uint32_t Kw = (b >> 4) & 0x07070707u;
            #pragma unroll
            for (int j = 0; j < 4; j++) {
                uint32_t s2 = 0x7540u | (uint32_t)j;
                float fE = __uint_as_float(__byte_perm(Ew, 0x4B000000u, s2)) - 8388608.f;
                float fC = __uint_as_float(__byte_perm(Cw, 0x4B000000u, s2)) - 8388608.f;
                float fK = __uint_as_float(__byte_perm(Kw, 0x4B000000u, s2)) - 8388608.f;
                gz[1 + (G << 3) + (half << 2) + j] =
                    fmaf(p00, fC, fmaf(p01, fE, p11 * fK));
            }
        }
    }

    // word halos via smem (neighbor word lives in another warp)
    sLo[w][yl] = gz[1];
    sHi[w][yl] = gz[32];
    __syncthreads();
    gz[0]  = sHi[(w + 7) & 7][yl];
    gz[33] = sLo[(w + 1) & 7][yl];

    #pragma unroll
    for (int k = 0; k < 8; k++) {
        float4 o;
        o.x = fmaf(a0, gz[4*k+1], a1 * (gz[4*k+0] + gz[4*k+2]));
        o.y = fmaf(a0, gz[4*k+2], a1 * (gz[4*k+1] + gz[4*k+3]));
        o.z = fmaf(a0, gz[4*k+3], a1 * (gz[4*k+2] + gz[4*k+4]));
        o.w = fmaf(a0, gz[4*k+4], a1 * (gz[4*k+3] + gz[4*k+5]));
        sOut[(yl << 6) + (((w << 3) + k) ^ yl)] = o;
    }
    __syncthreads();

    #pragma unroll
    for (int k2 = 0; k2 < 8; k2++) {
        int flat = (k2 << 8) + t;
        int yy2 = flat >> 6;
        int zg2 = flat & 63;
        float4 v = sOut[(yy2 << 6) + (zg2 ^ yy2)];
        out[(x << 14) | ((y0 + yy2) << 6) | zg2] = v;
    }
}

extern "C" void kernel_launch(void* const* d_in, const int* in_sizes, int n_in,
                              void* d_out, int out_size) {
    const float* xyz = (const float*)d_in[0];
    const float* vdw = (const float*)d_in[1];
    int n_atoms = in_sizes[1];

    // all double math on the HOST; device sees only f32
    double sigma = 1.1 / (100.0 / 256.0) / 4.0;
    double w = exp(-1.0 / (2.0 * sigma * sigma));
    double s = 1.0 + 2.0 * w;
    double a0d = 1.0 / s, a1d = w / s;
    float a0  = (float)a0d;
    float a1  = (float)a1d;
    float p00 = (float)(a0d * a0d);
    float p01 = (float)(a0d * a1d);
    float p11 = (float)(a1d * a1d);

    splat_kernel      <<<(n_atoms + 3) / 4, 256>>>(xyz, vdw, n_atoms);
    classify_kernel   <<<256, 256>>>();
    blur_fused5_kernel<<<2048, 256>>>((float4*)d_out, a0, a1, p00, p01, p11);
}

// round 12
// speedup vs baseline: 3.9580x; 1.1096x over previous
#include <cuda_runtime.h>
#include <math.h>
#include <stdint.h>

#define NG   256
#define NG3  16777216
#define NW   (NG3/32)           // 524288 z-words per mask
#define SP   0.390625f          // 100/256, exact in f32

// combined grid: per z-word, lo32 = occ bits, hi32 = prot bits
// zero-initialized at module load; blur kernel re-zeroes it each call.
static __device__ unsigned long long g_bits[NW];
static __device__ uint32_t           g_solvb[NW];

// smallest float T with (s < T) <=> (sqrt_rn(s) < R)
__device__ __forceinline__ float cut_threshold(float R) {
    float t = __fmul_rn(R, R);
    while (__fsqrt_rn(t) >= R)
        t = __uint_as_float(__float_as_uint(t) - 1u);
    while (__fsqrt_rn(__uint_as_float(__float_as_uint(t) + 1u)) < R)
        t = __uint_as_float(__float_as_uint(t) + 1u);
    return __uint_as_float(__float_as_uint(t) + 1u);
}

// exact reference predicate: fadd(rxy2, fmul(rz,rz)) < T, rz single-rounded
__device__ __forceinline__ bool cell_pass(int zc, float az, float rxy2, float T) {
    float rz = __fmaf_rn((float)zc, SP, -az);   // zc*SP exact => == fsub(fmul)
    float s  = __fadd_rn(rxy2, __fmul_rn(rz, rz));
    return s < T;
}

// contiguous passing z-interval [lo,hi] for threshold T (given rxy2 < T)
__device__ __forceinline__ void chord_bounds(float az, float rxy2, float T,
                                             int& lo, int& hi) {
    float t = __fsub_rn(T, rxy2);               // >= 0
    float h = __fsqrt_rn(t);
    int zl0 = (int)ceilf (__fmaf_rn(az - h, 2.56f, -1.25e-4f));
    int zh0 = (int)floorf(__fmaf_rn(az + h, 2.56f,  1.25e-4f));
    lo = cell_pass(zl0, az, rxy2, T) ? zl0 : zl0 + 1;
    hi = cell_pass(zh0, az, rxy2, T) ? zh0 : zh0 - 1;
}

// ---- splat: two warps per atom, fully unrolled independent iterations ----
__global__ void splat_kernel(const float* __restrict__ xyz,
                             const float* __restrict__ vdw,
                             int n_atoms) {
    int a = blockIdx.x * 4 + (threadIdx.x >> 6);
    if (a >= n_atoms) return;
    int lane = threadIdx.x & 63;
    float ax = xyz[3*a], ay = xyz[3*a+1], az = xyz[3*a+2];
    float vr = vdw[a];
    float R    = __fadd_rn(vr, 1.1f);
    float Tocc = cut_threshold(R);
    float Tpro = cut_threshold(vr);

    int bx = (int)floorf(__fdiv_rn(ax, SP));
    int by = (int)floorf(__fdiv_rn(ay, SP));
    int bz = (int)floorf(__fdiv_rn(az, SP));
    int zs = bz - 8;
    int s0 = zs & 255;
    int w0 = s0 >> 5, off = s0 & 31;

    #pragma unroll
    for (int it = 0; it < 5; ++it) {
        int p = lane + it * 64;
        if (p < 289) {
            int dx = p / 17 - 8;
            int dy = p % 17 - 8;
            int cx = bx + dx, cy = by + dy;
            // (cx*SP) exact in f32 => FMA == reference fsub(fmul(cx,SP), ax)
            float rx = __fmaf_rn((float)cx, SP, -ax);
            float ry = __fmaf_rn((float)cy, SP, -ay);
            float rxy2 = __fadd_rn(__fmul_rn(rx, rx), __fmul_rn(ry, ry));
            if (rxy2 < Tocc) {                    // exact cull (s >= rxy2)
                int lo, hi;
                chord_bounds(az, rxy2, Tocc, lo, hi);
                lo = max(lo, bz - 8);
                hi = min(hi, bz + 8);             // reference window truncation
                if (hi >= lo) {
                    unsigned mO = (2u << (hi - zs)) - (1u << (lo - zs));
                    unsigned mP = 0;
                    if (rxy2 < Tpro) {
                        int pl, ph;
                        chord_bounds(az, rxy2, Tpro, pl, ph);
                        pl = max(pl, bz - 8);
                        ph = min(ph, bz + 8);
                        if (ph >= pl) mP = (2u << (ph - zs)) - (1u << (pl - zs));
                    }
                    unsigned long long osh = ((unsigned long long)mO) << off;
                    unsigned long long psh = ((unsigned long long)mP) << off;
                    int colbase = ((cx & 255) << 8) | (cy & 255);
                    unsigned long long v0 = ((unsigned long long)(unsigned)psh << 32)
                                          |  (unsigned long long)(unsigned)osh;
                    unsigned long long v1 = ((unsigned long long)(unsigned)(psh >> 32) << 32)
                                          |  (unsigned long long)(unsigned)(osh >> 32);
                    if (v0) atomicOr(&g_bits[(w0 << 16) + colbase], v0);
                    if (v1) atomicOr(&g_bits[((((w0 + 1) & 7)) << 16) + colbase], v1);
                }
            }
        }
    }
}

// ---- classify: solv = ds | (nb & ~prot); coalesced (fast index -> gy) ----
__global__ void classify_kernel() {
    __shared__ uint32_t sD0[8 * 400];
    __shared__ uint32_t sD1[8 * 400];
    __shared__ uint32_t sD2[8 * 400];
    int bx0 = (blockIdx.x & 15) * 16;
    int by0 = (blockIdx.x >> 4) * 16;
    int t = threadIdx.x;

    for (int c = t; c < 400; c += 256) {
        int iy = c % 20, ix = c / 20;              // iy fast -> gy contiguous
        int gx = (bx0 + ix - 2) & 255;
        int gy = (by0 + iy - 2) & 255;
        int col = (gx << 8) | gy;
        uint32_t ds[8], d1[8], d2[8];
        #pragma unroll
        for (int i = 0; i < 8; i++)
            ds[i] = ~(uint32_t)g_bits[(i << 16) + col];
        #pragma unroll
        for (int i = 0; i < 8; i++)
            d1[i] = ds[i] | (ds[i] << 1) | (ds[(i+7)&7] >> 31)
                          | (ds[i] >> 1) | (ds[(i+1)&7] << 31);
        #pragma unroll
        for (int i = 0; i < 8; i++)
            d2[i] = d1[i] | (d1[i] << 1) | (d1[(i+7)&7] >> 31)
                          | (d1[i] >> 1) | (d1[(i+1)&7] << 31);
        #pragma unroll
        for (int i = 0; i < 8; i++) {
            sD0[i*400 + c] = ds[i];
            sD1[i*400 + c] = d1[i];
            sD2[i*400 + c] = d2[i];
        }
    }
    __syncthreads();

    int iy = (t & 15) + 2, ix = (t >> 4) + 2;      // iy fast -> gy contiguous
    int gx = (bx0 + ix - 2) & 255;
    int gy = (by0 + iy - 2) & 255;
    int col = (gx << 8) | gy;
    int cc = ix * 20 + iy;
    #pragma unroll
    for (int i = 0; i < 8; i++) {
        const uint32_t* D0 = sD0 + i * 400;
        const uint32_t* D1 = sD1 + i * 400;
        const uint32_t* D2 = sD2 + i * 400;
        uint32_t nb =
            D2[cc] | D2[cc+1]  | D2[cc-1]  | D2[cc+20] | D2[cc-20] |
            D1[cc+21] | D1[cc+19] | D1[cc-19] | D1[cc-21] |
            D1[cc+2]  | D1[cc-2]  | D1[cc+40] | D1[cc-40] |
            D0[cc+22] | D0[cc+18] | D0[cc-18] | D0[cc-22] |
            D0[cc+41] | D0[cc+39] | D0[cc-39] | D0[cc-41];
        uint32_t p = (uint32_t)(g_bits[(i << 16) + col] >> 32);
        g_solvb[(i << 16) + col] = D0[cc] | (nb & ~p);
    }
}

// CSA of 4 one-bit vectors: sum = lo + 2*mid + 4*hi
__device__ __forceinline__ void csa4(uint32_t a, uint32_t b, uint32_t c, uint32_t d,
                                     uint32_t& lo, uint32_t& mid, uint32_t& hi) {
    uint32_t s1 = a ^ b ^ c;
    uint32_t m1 = (a & b) | (c & (a | b));
    uint32_t cy = s1 & d;
    lo  = s1 ^ d;
    mid = m1 ^ cy;
    hi  = m1 & cy;
}

// ---- fused 27-tap blur v6: vectorized staging; re-zeroes g_bits ----
__global__ __launch_bounds__(256)
void blur_fused6_kernel(float4* __restrict__ out,
                        float a0, float a1,
                        float p00, float p01, float p11) {
    __shared__ uint32_t sB[8][3][40];     // interior at [4+i], halos [3] and [36]
    __shared__ float    sHi[8][32];
    __shared__ float    sLo[8][32];
    __shared__ float4   sOut[2048];

    int t  = threadIdx.x;
    int x  = blockIdx.x >> 3;
    int y0 = (blockIdx.x & 7) << 5;

    // re-zero splat grid for the next kernel_launch call
    g_bits[blockIdx.x * 256 + t] = 0ULL;

    if (t < 192) {                         // interior: 24 (w,xi) x 8 uint4
        int combo = t >> 3;                // 0..23
        int q     = t & 7;                 // 0..7
        int w  = combo / 3;
        int xi = combo % 3;
        int gx = (x + xi - 1) & 255;
        const uint4* src = reinterpret_cast<const uint4*>(
            &g_solvb[(w << 16) | (gx << 8) | y0]);
        *reinterpret_cast<uint4*>(&sB[w][xi][4 + (q << 2)]) = src[q];
    } else if (t < 240) {                  // halos: 24 combos x 2 sides
        int e = t - 192;
        int combo = e >> 1;
        int side  = e & 1;
        int w  = combo / 3;
        int xi = combo % 3;
        int gx = (x + xi - 1) & 255;
        int gy = side ? ((y0 + 32) & 255) : ((y0 - 1) & 255);
        sB[w][xi][side ? 36 : 3] = g_solvb[(w << 16) | (gx << 8) | gy];
    }
    __syncthreads();

    int yl = t & 31;          // lane = y
    int w  = t >> 5;          // warp = word

    uint32_t cc = sB[w][1][4+yl];
    uint32_t ea = sB[w][0][4+yl], eb = sB[w][2][4+yl];
    uint32_t ec = sB[w][1][3+yl], ed = sB[w][1][5+yl];
    uint32_t ka = sB[w][0][3+yl], kb = sB[w][2][3+yl];
    uint32_t kc = sB[w][0][5+yl], kd = sB[w][2][5+yl];

    float gz[34];
    uint32_t E0, E1, E2, K0, K1, K2;
    csa4(ea, eb, ec, ed, E0, E1, E2);
    csa4(ka, kb, kc, kd, K0, K1, K2);
    #pragma unroll
    for (int G = 0; G < 4; G++) {
        uint32_t sel = (uint32_t)G | ((uint32_t)(4 + G) << 4);
        uint32_t t01 = __byte_perm(E0, E1, sel);
        uint32_t t23 = __byte_perm(E2, cc, sel);
        uint32_t t45 = __byte_perm(K0, K1, sel);
        uint32_t t67 = __byte_perm(K2, 0u, sel);
        uint32_t lo  = __byte_perm(t01, t23, 0x5410);
        uint32_t hi  = __byte_perm(t45, t67, 0x5410);
        unsigned long long xb = (unsigned long long)lo
                              | ((unsigned long long)hi << 32);
        unsigned long long yb;
        yb = (xb ^ (xb >> 7))  & 0x00AA00AA00AA00AAULL; xb ^= yb ^ (yb << 7);
        yb = (xb ^ (xb >> 14)) & 0x0000CCCC0000CCCCULL; xb ^= yb ^ (yb << 14);
        yb = (xb ^ (xb >> 28)) & 0x00000000F0F0F0F0ULL; xb ^= yb ^ (yb << 28);
        uint32_t blo = (uint32_t)xb, bhi = (uint32_t)(xb >> 32);
        #pragma unroll
        for (int half = 0; half < 2; half++) {
            uint32_t b  = half ? bhi : blo;
            uint32_t Ew = b & 0x07070707u;
            uint32_t Cw = (b >> 3) & 0x01010101u;
            uint32_t Kw = (b >> 4) & 0x07070707u;
            #pragma unroll
            for (int j = 0; j < 4; j++) {
                uint32_t s2 = 0x7540u | (uint32_t)j;
                float fE = __uint_as_float(__byte_perm(Ew, 0x4B000000u, s2)) - 8388608.f;
                float fC = __uint_as_float(__byte_perm(Cw, 0x4B000000u, s2)) - 8388608.f;
                float fK = __uint_as_float(__byte_perm(Kw, 0x4B000000u, s2)) - 8388608.f;
                gz[1 + (G << 3) + (half << 2) + j] =
                    fmaf(p00, fC, fmaf(p01, fE, p11 * fK));
            }
        }
    }

    // word halos via smem (neighbor word lives in another warp)
    sLo[w][yl] = gz[1];
    sHi[w][yl] = gz[32];
    __syncthreads();
    gz[0]  = sHi[(w + 7) & 7][yl];
    gz[33] = sLo[(w + 1) & 7][yl];

    #pragma unroll
    for (int k = 0; k < 8; k++) {
        float4 o;
        o.x = fmaf(a0, gz[4*k+1], a1 * (gz[4*k+0] + gz[4*k+2]));
        o.y = fmaf(a0, gz[4*k+2], a1 * (gz[4*k+1] + gz[4*k+3]));
        o.z = fmaf(a0, gz[4*k+3], a1 * (gz[4*k+2] + gz[4*k+4]));
        o.w = fmaf(a0, gz[4*k+4], a1 * (gz[4*k+3] + gz[4*k+5]));
        sOut[(yl << 6) + (((w << 3) + k) ^ yl)] = o;
    }
    __syncthreads();

    #pragma unroll
    for (int k2 = 0; k2 < 8; k2++) {
        int flat = (k2 << 8) + t;
        int yy2 = flat >> 6;
        int zg2 = flat & 63;
        float4 v = sOut[(yy2 << 6) + (zg2 ^ yy2)];
        out[(x << 14) | ((y0 + yy2) << 6) | zg2] = v;
    }
}

extern "C" void kernel_launch(void* const* d_in, const int* in_sizes, int n_in,
                              void* d_out, int out_size) {
    const float* xyz = (const float*)d_in[0];
    const float* vdw = (const float*)d_in[1];
    int n_atoms = in_sizes[1];

    // all double math on the HOST; device sees only f32
    double sigma = 1.1 / (100.0 / 256.0) / 4.0;
    double w = exp(-1.0 / (2.0 * sigma * sigma));
    double s = 1.0 + 2.0 * w;
    double a0d = 1.0 / s, a1d = w / s;
    float a0  = (float)a0d;
    float a1  = (float)a1d;
    float p00 = (float)(a0d * a0d);
    float p01 = (float)(a0d * a1d);
    float p11 = (float)(a1d * a1d);

    splat_kernel      <<<(n_atoms + 3) / 4, 256>>>(xyz, vdw, n_atoms);
    classify_kernel   <<<256, 256>>>();
    blur_fused6_kernel<<<2048, 256>>>((float4*)d_out, a0, a1, p00, p01, p11);
}

// round 13
// speedup vs baseline: 4.1875x; 1.0580x over previous
#include <cuda_runtime.h>
#include <math.h>
#include <stdint.h>

#define NG   256
#define NG3  16777216
#define NW   (NG3/32)           // 524288 z-words per mask
#define SP   0.390625f          // 100/256, exact in f32

// combined grid: per z-word, lo32 = occ bits, hi32 = prot bits
// zero-initialized at module load; blur kernel re-zeroes it each call.
static __device__ unsigned long long g_bits[NW];
static __device__ uint32_t           g_solvb[NW];

// smallest float T with (s < T) <=> (sqrt_rn(s) < R)
__device__ __forceinline__ float cut_threshold(float R) {
    float t = __fmul_rn(R, R);
    while (__fsqrt_rn(t) >= R)
        t = __uint_as_float(__float_as_uint(t) - 1u);
    while (__fsqrt_rn(__uint_as_float(__float_as_uint(t) + 1u)) < R)
        t = __uint_as_float(__float_as_uint(t) + 1u);
    return __uint_as_float(__float_as_uint(t) + 1u);
}

// exact reference predicate: fadd(rxy2, fmul(rz,rz)) < T, rz single-rounded
__device__ __forceinline__ bool cell_pass(int zc, float az, float rxy2, float T) {
    float rz = __fmaf_rn((float)zc, SP, -az);   // zc*SP exact => == fsub(fmul)
    float s  = __fadd_rn(rxy2, __fmul_rn(rz, rz));
    return s < T;
}

// contiguous passing z-interval [lo,hi] for threshold T (given rxy2 < T)
__device__ __forceinline__ void chord_bounds(float az, float rxy2, float T,
                                             int& lo, int& hi) {
    float t = __fsub_rn(T, rxy2);               // >= 0
    float h = __fsqrt_rn(t);
    int zl0 = (int)ceilf (__fmaf_rn(az - h, 2.56f, -1.25e-4f));
    int zh0 = (int)floorf(__fmaf_rn(az + h, 2.56f,  1.25e-4f));
    lo = cell_pass(zl0, az, rxy2, T) ? zl0 : zl0 + 1;
    hi = cell_pass(zh0, az, rxy2, T) ? zh0 : zh0 - 1;
}

// ---- splat: two warps per atom, fully unrolled independent iterations ----
__global__ void splat_kernel(const float* __restrict__ xyz,
                             const float* __restrict__ vdw,
                             int n_atoms) {
    int a = blockIdx.x * 4 + (threadIdx.x >> 6);
    if (a >= n_atoms) return;
    int lane = threadIdx.x & 63;
    float ax = xyz[3*a], ay = xyz[3*a+1], az = xyz[3*a+2];
    float vr = vdw[a];
    float R    = __fadd_rn(vr, 1.1f);
    float Tocc = cut_threshold(R);
    float Tpro = cut_threshold(vr);

    int bx = (int)floorf(__fdiv_rn(ax, SP));
    int by = (int)floorf(__fdiv_rn(ay, SP));
    int bz = (int)floorf(__fdiv_rn(az, SP));
    int zs = bz - 8;
    int s0 = zs & 255;
    int w0 = s0 >> 5, off = s0 & 31;

    #pragma unroll
    for (int it = 0; it < 5; ++it) {
        int p = lane + it * 64;
        // iterations 0..3: p <= 255 < 289 always (lane <= 63)
        if (it < 4 || p < 289) {
            int dx = p / 17 - 8;
            int dy = p % 17 - 8;
            int cx = bx + dx, cy = by + dy;
            // (cx*SP) exact in f32 => FMA == reference fsub(fmul(cx,SP), ax)
            float rx = __fmaf_rn((float)cx, SP, -ax);
            float ry = __fmaf_rn((float)cy, SP, -ay);
            float rxy2 = __fadd_rn(__fmul_rn(rx, rx), __fmul_rn(ry, ry));
            if (rxy2 < Tocc) {                    // exact cull (s >= rxy2)
                int lo, hi;
                chord_bounds(az, rxy2, Tocc, lo, hi);
                lo = max(lo, bz - 8);
                hi = min(hi, bz + 8);             // reference window truncation
                if (hi >= lo) {
                    unsigned mO = (2u << (hi - zs)) - (1u << (lo - zs));
                    unsigned mP = 0;
                    if (rxy2 < Tpro) {
                        int pl, ph;
                        chord_bounds(az, rxy2, Tpro, pl, ph);
                        pl = max(pl, bz - 8);
                        ph = min(ph, bz + 8);
                        if (ph >= pl) mP = (2u << (ph - zs)) - (1u << (pl - zs));
                    }
                    unsigned long long osh = ((unsigned long long)mO) << off;
                    unsigned long long psh = ((unsigned long long)mP) << off;
                    int colbase = ((cx & 255) << 8) | (cy & 255);
                    unsigned long long v0 = ((unsigned long long)(unsigned)psh << 32)
                                          |  (unsigned long long)(unsigned)osh;
                    unsigned long long v1 = ((unsigned long long)(unsigned)(psh >> 32) << 32)
                                          |  (unsigned long long)(unsigned)(osh >> 32);
                    if (v0) atomicOr(&g_bits[(w0 << 16) + colbase], v0);
                    if (v1) atomicOr(&g_bits[((((w0 + 1) & 7)) << 16) + colbase], v1);
                }
            }
        }
    }
}

// ---- classify: solv = ds | (nb & ~prot); coalesced (fast index -> gy) ----
__global__ void classify_kernel() {
    __shared__ uint32_t sD0[8 * 400];
    __shared__ uint32_t sD1[8 * 400];
    __shared__ uint32_t sD2[8 * 400];
    int bx0 = (blockIdx.x & 15) * 16;
    int by0 = (blockIdx.x >> 4) * 16;
    int t = threadIdx.x;

    for (int c = t; c < 400; c += 256) {
        int iy = c % 20, ix = c / 20;              // iy fast -> gy contiguous
        int gx = (bx0 + ix - 2) & 255;
        int gy = (by0 + iy - 2) & 255;
        int col = (gx << 8) | gy;
        uint32_t ds[8], d1[8], d2[8];
        #pragma unroll
        for (int i = 0; i < 8; i++)
            ds[i] = ~(uint32_t)g_bits[(i << 16) + col];
        #pragma unroll
        for (int i = 0; i < 8; i++)
            d1[i] = ds[i] | (ds[i] << 1) | (ds[(i+7)&7] >> 31)
                          | (ds[i] >> 1) | (ds[(i+1)&7] << 31);
        #pragma unroll
        for (int i = 0; i < 8; i++)
            d2[i] = d1[i] | (d1[i] << 1) | (d1[(i+7)&7] >> 31)
                          | (d1[i] >> 1) | (d1[(i+1)&7] << 31);
        #pragma unroll
        for (int i = 0; i < 8; i++) {
            sD0[i*400 + c] = ds[i];
            sD1[i*400 + c] = d1[i];
            sD2[i*400 + c] = d2[i];
        }
    }
    __syncthreads();

    int iy = (t & 15) + 2, ix = (t >> 4) + 2;      // iy fast -> gy contiguous
    int gx = (bx0 + ix - 2) & 255;
    int gy = (by0 + iy - 2) & 255;
    int col = (gx << 8) | gy;
    int cc = ix * 20 + iy;
    #pragma unroll
    for (int i = 0; i < 8; i++) {
        const uint32_t* D0 = sD0 + i * 400;
        const uint32_t* D1 = sD1 + i * 400;
        const uint32_t* D2 = sD2 + i * 400;
        uint32_t nb =
            D2[cc] | D2[cc+1]  | D2[cc-1]  | D2[cc+20] | D2[cc-20] |
            D1[cc+21] | D1[cc+19] | D1[cc-19] | D1[cc-21] |
            D1[cc+2]  | D1[cc-2]  | D1[cc+40] | D1[cc-40] |
            D0[cc+22] | D0[cc+18] | D0[cc-18] | D0[cc-22] |
            D0[cc+41] | D0[cc+39] | D0[cc-39] | D0[cc-41];
        uint32_t p = (uint32_t)(g_bits[(i << 16) + col] >> 32);
        g_solvb[(i << 16) + col] = D0[cc] | (nb & ~p);
    }
}

// CSA of 4 one-bit vectors: sum = lo + 2*mid + 4*hi
__device__ __forceinline__ void csa4(uint32_t a, uint32_t b, uint32_t c, uint32_t d,
                                     uint32_t& lo, uint32_t& mid, uint32_t& hi) {
    uint32_t s1 = a ^ b ^ c;
    uint32_t m1 = (a & b) | (c & (a | b));
    uint32_t cy = s1 & d;
    lo  = s1 ^ d;
    mid = m1 ^ cy;
    hi  = m1 & cy;
}

// ---- fused 27-tap blur v7: per-cell 7-bit index -> 128-entry f32 LUT ----
// transposed byte = E + 8*C + 16*K (<= 76); LUT holds the exact expression
// fmaf(p00,C, fmaf(p01,E, p11*K)) -> bit-identical to computing per cell.
__global__ __launch_bounds__(256)
void blur_fused7_kernel(float4* __restrict__ out,
                        float a0, float a1,
                        float p00, float p01, float p11) {
    __shared__ uint32_t sB[8][3][40];     // interior at [4+i], halos [3] and [36]
    __shared__ float    sLut[128];
    __shared__ float    sHi[8][32];
    __shared__ float    sLo[8][32];
    __shared__ float4   sOut[2048];

    int t  = threadIdx.x;
    int x  = blockIdx.x >> 3;
    int y0 = (blockIdx.x & 7) << 5;

    // re-zero splat grid for the next kernel_launch call
    g_bits[blockIdx.x * 256 + t] = 0ULL;

    if (t < 128) {
        float fE = (float)( t       & 7);
        float fC = (float)((t >> 3) & 1);
        float fK = (float)((t >> 4) & 7);
        sLut[t] = fmaf(p00, fC, fmaf(p01, fE, p11 * fK));
    }
    if (t < 192) {                         // interior: 24 (w,xi) x 8 uint4
        int combo = t >> 3;                // 0..23
        int q     = t & 7;                 // 0..7
        int w  = combo / 3;
        int xi = combo % 3;
        int gx = (x + xi - 1) & 255;
        const uint4* src = reinterpret_cast<const uint4*>(
            &g_solvb[(w << 16) | (gx << 8) | y0]);
        *reinterpret_cast<uint4*>(&sB[w][xi][4 + (q << 2)]) = src[q];
    } else if (t < 240) {                  // halos: 24 combos x 2 sides
        int e = t - 192;
        int combo = e >> 1;
        int side  = e & 1;
        int w  = combo / 3;
        int xi = combo % 3;
        int gx = (x + xi - 1) & 255;
        int gy = side ? ((y0 + 32) & 255) : ((y0 - 1) & 255);
        sB[w][xi][side ? 36 : 3] = g_solvb[(w << 16) | (gx << 8) | gy];
    }
    __syncthreads();

    int yl = t & 31;          // lane = y
    int w  = t >> 5;          // warp = word

    uint32_t cc = sB[w][1][4+yl];
    uint32_t ea = sB[w][0][4+yl], eb = sB[w][2][4+yl];
    uint32_t ec = sB[w][1][3+yl], ed = sB[w][1][5+yl];
    uint32_t ka = sB[w][0][3+yl], kb = sB[w][2][3+yl];
    uint32_t kc = sB[w][0][5+yl], kd = sB[w][2][5+yl];

    float gz[34];
    uint32_t E0, E1, E2, K0, K1, K2;
    csa4(ea, eb, ec, ed, E0, E1, E2);
    csa4(ka, kb, kc, kd, K0, K1, K2);
    #pragma unroll
    for (int G = 0; G < 4; G++) {
        uint32_t sel = (uint32_t)G | ((uint32_t)(4 + G) << 4);
        uint32_t t01 = __byte_perm(E0, E1, sel);
        uint32_t t23 = __byte_perm(E2, cc, sel);
        uint32_t t45 = __byte_perm(K0, K1, sel);
        uint32_t t67 = __byte_perm(K2, 0u, sel);
        uint32_t lo  = __byte_perm(t01, t23, 0x5410);
        uint32_t hi  = __byte_perm(t45, t67, 0x5410);
        unsigned long long xb = (unsigned long long)lo
                              | ((unsigned long long)hi << 32);
        unsigned long long yb;
        yb = (xb ^ (xb >> 7))  & 0x00AA00AA00AA00AAULL; xb ^= yb ^ (yb << 7);
        yb = (xb ^ (xb >> 14)) & 0x0000CCCC0000CCCCULL; xb ^= yb ^ (yb << 14);
        yb = (xb ^ (xb >> 28)) & 0x00000000F0F0F0F0ULL; xb ^= yb ^ (yb << 28);
        uint32_t blo = (uint32_t)xb, bhi = (uint32_t)(xb >> 32);
        float* g = &gz[1 + (G << 3)];
        g[0] = sLut[ blo        & 0xFFu];
        g[1] = sLut[(blo >>  8) & 0xFFu];
        g[2] = sLut[(blo >> 16) & 0xFFu];
        g[3] = sLut[ blo >> 24        ];
        g[4] = sLut[ bhi        & 0xFFu];
        g[5] = sLut[(bhi >>  8) & 0xFFu];
        g[6] = sLut[(bhi >> 16) & 0xFFu];
        g[7] = sLut[ bhi >> 24        ];
    }

    // word halos via smem (neighbor word lives in another warp)
    sLo[w][yl] = gz[1];
    sHi[w][yl] = gz[32];
    __syncthreads();
    gz[0]  = sHi[(w + 7) & 7][yl];
    gz[33] = sLo[(w + 1) & 7][yl];

    #pragma unroll
    for (int k = 0; k < 8; k++) {
        float4 o;
        o.x = fmaf(a0, gz[4*k+1], a1 * (gz[4*k+0] + gz[4*k+2]));
        o.y = fmaf(a0, gz[4*k+2], a1 * (gz[4*k+1] + gz[4*k+3]));
        o.z = fmaf(a0, gz[4*k+3], a1 * (gz[4*k+2] + gz[4*k+4]));
        o.w = fmaf(a0, gz[4*k+4], a1 * (gz[4*k+3] + gz[4*k+5]));
        sOut[(yl << 6) + (((w << 3) + k) ^ yl)] = o;
    }
    __syncthreads();

    #pragma unroll
    for (int k2 = 0; k2 < 8; k2++) {
        int flat = (k2 << 8) + t;
        int yy2 = flat >> 6;
        int zg2 = flat & 63;
        float4 v = sOut[(yy2 << 6) + (zg2 ^ yy2)];
        out[(x << 14) | ((y0 + yy2) << 6) | zg2] = v;
    }
}

extern "C" void kernel_launch(void* const* d_in, const int* in_sizes, int n_in,
                              void* d_out, int out_size) {
    const float* xyz = (const float*)d_in[0];
    const float* vdw = (const float*)d_in[1];
    int n_atoms = in_sizes[1];

    // all double math on the HOST; device sees only f32
    double sigma = 1.1 / (100.0 / 256.0) / 4.0;
    double w = exp(-1.0 / (2.0 * sigma * sigma));
    double s = 1.0 + 2.0 * w;
    double a0d = 1.0 / s, a1d = w / s;
    float a0  = (float)a0d;
    float a1  = (float)a1d;
    float p00 = (float)(a0d * a0d);
    float p01 = (float)(a0d * a1d);
    float p11 = (float)(a1d * a1d);

    splat_kernel      <<<(n_atoms + 3) / 4, 256>>>(xyz, vdw, n_atoms);
    classify_kernel   <<<256, 256>>>();
    blur_fused7_kernel<<<2048, 256>>>((float4*)d_out, a0, a1, p00, p01, p11);
}